// round 8
// baseline (speedup 1.0000x reference)
#include <cuda_runtime.h>
#include <cuda_fp16.h>
#include <math.h>

#define NUM_N 100000
#define NUM_E 1600000
#define NUM_G 128
#define D_IN 128

#define GRID  148
#define TPB   1024
#define GT    (GRID * TPB)        // 151552 threads
#define NWARP (GT / 32)           // 4736 warps
#define CHUNK 676                 // 148*676 >= NUM_N
#define NE2   (NUM_E / 2)         // 800000 edge pairs

// -------- device scratch (statics start zeroed) ----------------------------
__device__ int    g_bar[8];
__device__ int    g_batch[NUM_N];
__device__ int    g_deg[NUM_N];
__device__ float  g_dinv[NUM_N];
__device__ int    g_woff[NUM_N];
__device__ int    g_csrc[NUM_E];
__device__ int    g_bsum[GRID];
__device__ int    g_pcnt[NUM_G];
__device__ int    g_pcnt2[NUM_G];
__device__ int    g_boff[NUM_G];
__device__ int    g_boff2[NUM_G];
__device__ int    g_bnode[NUM_N];
__device__ __half g_h1h[NUM_N * 16];   // (x @ W1) * dinv, fp16
__device__ __half g_qh [NUM_N * 16];   // relu(layer1) * dinv, fp16
__device__ float  g_r  [NUM_N * 16];   // layer2 aggregate, fp32

// -------- software grid barrier -------------------------------------------
__device__ __forceinline__ void grid_sync(int j) {
    __syncthreads();
    __threadfence();
    if (threadIdx.x == 0) {
        if (atomicAdd(&g_bar[j], 1) == GRID - 1) {
            atomicExch(&g_bar[(j + 4) % 6], 0);
        } else {
            while (*((volatile int*)&g_bar[j]) < GRID) { }
        }
    }
    __syncthreads();
    __threadfence();
}

__device__ __forceinline__ void gather16h(const __half* base, int s, int sub,
                                          float& ax, float& ay, float& az, float& aw) {
    uint2 u = ((const uint2*)(base))[s * 4 + sub];
    float2 f0 = __half22float2(*(__half2*)&u.x);
    float2 f1 = __half22float2(*(__half2*)&u.y);
    ax += f0.x; ay += f0.y; az += f1.x; aw += f1.y;
}

// halving butterfly: 16 per-lane partials -> 16 sums; result for output j
// ends on lane pairs, value at even lanes with j = lane/2 (returned on all).
__device__ __forceinline__ float butterfly16(float a[16], int lane) {
    {
        float t[16];
        #pragma unroll
        for (int i = 0; i < 16; i++) t[i] = __shfl_xor_sync(~0u, a[i], 16);
        if ((lane & 16) == 0) {
            #pragma unroll
            for (int i = 0; i < 8; i++) a[i] += t[i];
        } else {
            #pragma unroll
            for (int i = 0; i < 8; i++) a[i] = a[i + 8] + t[i + 8];
        }
    }
    {
        float t[8];
        #pragma unroll
        for (int i = 0; i < 8; i++) t[i] = __shfl_xor_sync(~0u, a[i], 8);
        if ((lane & 8) == 0) {
            #pragma unroll
            for (int i = 0; i < 4; i++) a[i] += t[i];
        } else {
            #pragma unroll
            for (int i = 0; i < 4; i++) a[i] = a[i + 4] + t[i + 4];
        }
    }
    {
        float t[4];
        #pragma unroll
        for (int i = 0; i < 4; i++) t[i] = __shfl_xor_sync(~0u, a[i], 4);
        if ((lane & 4) == 0) { a[0] += t[0]; a[1] += t[1]; }
        else                 { a[0] = a[2] + t[2]; a[1] = a[3] + t[3]; }
    }
    {
        float t0 = __shfl_xor_sync(~0u, a[0], 2);
        float t1 = __shfl_xor_sync(~0u, a[1], 2);
        if ((lane & 2) == 0) a[0] += t0; else a[0] = a[1] + t1;
    }
    a[0] += __shfl_xor_sync(~0u, a[0], 1);
    return a[0];
}

__global__ __launch_bounds__(TPB, 1) void mega_kernel(
    const float* __restrict__ x, const void* ei, const void* bat,
    const float* __restrict__ W1, const float* __restrict__ b1,
    const float* __restrict__ W2, const float* __restrict__ b2,
    const float* __restrict__ LW1, const float* __restrict__ Lb1,
    const float* __restrict__ LW2, const float* __restrict__ Lb2,
    float* __restrict__ out)
{
    __shared__ float4 w1s[512];
    __shared__ float4 w2s[512];
    __shared__ float4 red[1024];
    __shared__ int    wsum[32];
    __shared__ int    s_i32, s_base;
    __shared__ float  ps[128], z1[128], z2[2];

    const int tid  = threadIdx.x, bid = blockIdx.x;
    const int lane = tid & 31,    wid = tid >> 5;
    const int gth  = bid * TPB + tid;
    const int gw   = gth >> 5;

    // ---- detect int64 vs int32 index layout ----
    if (tid == 0) s_i32 = 0;
    __syncthreads();
    if (tid < 64) {
        long long v = ((const long long*)ei)[(size_t)tid * (NUM_E / 64)];
        if (v < 0 || v >= (long long)NUM_N) s_i32 = 1;
    }
    __syncthreads();
    const bool f64 = (s_i32 == 0);

    // ================= P0: histograms (4 edges/thread/iter) ================
    for (int i = gth; i < NE2; i += 2 * GT) {
        int d0, d1;
        if (f64) { int4 v = ((const int4*)ei)[NE2 + i]; d0 = v.x; d1 = v.z; }
        else     { int2 v = ((const int2*)ei)[NE2 + i]; d0 = v.x; d1 = v.y; }
        int i2 = i + GT;
        int d2 = -1, d3 = -1;
        if (i2 < NE2) {
            if (f64) { int4 v = ((const int4*)ei)[NE2 + i2]; d2 = v.x; d3 = v.z; }
            else     { int2 v = ((const int2*)ei)[NE2 + i2]; d2 = v.x; d3 = v.y; }
        }
        atomicAdd(&g_deg[d0], 1);
        atomicAdd(&g_deg[d1], 1);
        if (i2 < NE2) { atomicAdd(&g_deg[d2], 1); atomicAdd(&g_deg[d3], 1); }
    }
    for (int i = gth; i < NUM_N; i += GT) {
        int b = f64 ? (int)((const long long*)bat)[i] : ((const int*)bat)[i];
        g_batch[i] = b;
        atomicAdd(&g_pcnt[b], 1);
    }
    grid_sync(0);

    // ================= P1: block-local scan of deg (+dinv, batch scan) =====
    const int node = bid * CHUNK + tid;
    const bool nvalid = (tid < CHUNK) && (node < NUM_N);
    int deg = nvalid ? g_deg[node] : 0;
    int v = deg;
    #pragma unroll
    for (int o = 1; o < 32; o <<= 1) {
        int n = __shfl_up_sync(~0u, v, o);
        if (lane >= o) v += n;
    }
    if (lane == 31) wsum[wid] = v;
    __syncthreads();
    if (wid == 0) {
        int wv = wsum[lane];
        #pragma unroll
        for (int o = 1; o < 32; o <<= 1) {
            int n = __shfl_up_sync(~0u, wv, o);
            if (lane >= o) wv += n;
        }
        wsum[lane] = wv;
    }
    __syncthreads();
    const int ex_local = (wid ? wsum[wid - 1] : 0) + v - deg;
    if (tid == 0) g_bsum[bid] = wsum[31];
    if (nvalid) g_dinv[node] = rsqrtf((float)deg + 1.f);
    if (bid == 0 && wid == 31) {
        int p0 = g_pcnt[lane*4+0], p1 = g_pcnt[lane*4+1];
        int p2 = g_pcnt[lane*4+2], p3 = g_pcnt[lane*4+3];
        int t1 = p0 + p1, t2 = t1 + p2, t3 = t2 + p3;
        int vv = t3;
        #pragma unroll
        for (int o = 1; o < 32; o <<= 1) {
            int n = __shfl_up_sync(~0u, vv, o);
            if (lane >= o) vv += n;
        }
        int exb = vv - t3;
        g_boff [lane*4+0] = exb;      g_boff2[lane*4+0] = exb;
        g_boff [lane*4+1] = exb+p0;   g_boff2[lane*4+1] = exb+p0;
        g_boff [lane*4+2] = exb+t1;   g_boff2[lane*4+2] = exb+t1;
        g_boff [lane*4+3] = exb+t2;   g_boff2[lane*4+3] = exb+t2;
        g_pcnt2[lane*4+0] = p0; g_pcnt2[lane*4+1] = p1;
        g_pcnt2[lane*4+2] = p2; g_pcnt2[lane*4+3] = p3;
    }
    grid_sync(1);

    // ================= P2: per-block global base, write woff ===============
    if (wid == 0) {
        int s = 0;
        for (int i = lane; i < bid; i += 32) s += g_bsum[i];
        #pragma unroll
        for (int o = 16; o; o >>= 1) s += __shfl_xor_sync(~0u, s, o);
        if (lane == 0) s_base = s;
    }
    __syncthreads();
    if (nvalid) g_woff[node] = s_base + ex_local;
    grid_sync(2);

    // ================= P3: scatter (4 edges/thread/iter) + bnode + gemm1 ===
    for (int i = gth; i < NE2; i += 2 * GT) {
        int s0, s1, d0, d1;
        if (f64) {
            int4 sv = ((const int4*)ei)[i];       s0 = sv.x; s1 = sv.z;
            int4 dv = ((const int4*)ei)[NE2 + i]; d0 = dv.x; d1 = dv.z;
        } else {
            int2 sv = ((const int2*)ei)[i];       s0 = sv.x; s1 = sv.y;
            int2 dv = ((const int2*)ei)[NE2 + i]; d0 = dv.x; d1 = dv.y;
        }
        int i2 = i + GT;
        int s2 = 0, s3 = 0, d2 = 0, d3 = 0;
        bool have2 = (i2 < NE2);
        if (have2) {
            if (f64) {
                int4 sv = ((const int4*)ei)[i2];       s2 = sv.x; s3 = sv.z;
                int4 dv = ((const int4*)ei)[NE2 + i2]; d2 = dv.x; d3 = dv.z;
            } else {
                int2 sv = ((const int2*)ei)[i2];       s2 = sv.x; s3 = sv.y;
                int2 dv = ((const int2*)ei)[NE2 + i2]; d2 = dv.x; d3 = dv.y;
            }
        }
        int p0 = atomicAdd(&g_woff[d0], 1);
        int p1 = atomicAdd(&g_woff[d1], 1);
        int p2 = 0, p3 = 0;
        if (have2) {
            p2 = atomicAdd(&g_woff[d2], 1);
            p3 = atomicAdd(&g_woff[d3], 1);
        }
        g_csrc[p0] = s0;
        g_csrc[p1] = s1;
        if (have2) { g_csrc[p2] = s2; g_csrc[p3] = s3; }
    }
    for (int i = gth; i < NUM_N; i += GT) {
        int b = g_batch[i];
        g_bnode[atomicAdd(&g_boff[b], 1)] = i;
    }
    for (int i = tid; i < 512; i += TPB) w1s[i] = ((const float4*)W1)[i];
    __syncthreads();
    {   // gemm1: TWO nodes per warp-iteration share each W1 LDS (smem /2)
        for (int w = gw; w < NUM_N; w += 2 * NWARP) {
            int wb = w + NWARP;
            bool hb = (wb < NUM_N);          // warp-uniform
            float4 xa = ((const float4*)x)[(size_t)w * 32 + lane];
            float4 xb = hb ? ((const float4*)x)[(size_t)wb * 32 + lane] : xa;
            float a0[16], a1[16];
            #pragma unroll
            for (int j = 0; j < 16; j++) { a0[j] = 0.f; a1[j] = 0.f; }
            float xs0[4] = {xa.x, xa.y, xa.z, xa.w};
            float xs1[4] = {xb.x, xb.y, xb.z, xb.w};
            int kb4 = lane * 16;
            #pragma unroll
            for (int kk = 0; kk < 4; kk++) {
                float c0 = xs0[kk], c1 = xs1[kk];
                #pragma unroll
                for (int q = 0; q < 4; q++) {
                    float4 wv = w1s[kb4 + kk * 4 + q];
                    a0[q*4+0] = fmaf(c0, wv.x, a0[q*4+0]);
                    a0[q*4+1] = fmaf(c0, wv.y, a0[q*4+1]);
                    a0[q*4+2] = fmaf(c0, wv.z, a0[q*4+2]);
                    a0[q*4+3] = fmaf(c0, wv.w, a0[q*4+3]);
                    a1[q*4+0] = fmaf(c1, wv.x, a1[q*4+0]);
                    a1[q*4+1] = fmaf(c1, wv.y, a1[q*4+1]);
                    a1[q*4+2] = fmaf(c1, wv.z, a1[q*4+2]);
                    a1[q*4+3] = fmaf(c1, wv.w, a1[q*4+3]);
                }
            }
            {
                float r0 = butterfly16(a0, lane) * g_dinv[w];
                float rhi = __shfl_down_sync(~0u, r0, 2);
                if ((lane & 3) == 0)
                    ((__half2*)g_h1h)[(size_t)w * 8 + (lane >> 2)] =
                        __floats2half2_rn(r0, rhi);
            }
            if (hb) {
                float r1 = butterfly16(a1, lane) * g_dinv[wb];
                float rhi = __shfl_down_sync(~0u, r1, 2);
                if ((lane & 3) == 0)
                    ((__half2*)g_h1h)[(size_t)wb * 8 + (lane >> 2)] =
                        __floats2half2_rn(r1, rhi);
            }
        }
    }
    grid_sync(3);

    // ================= P4: prop1 (2-deep pipelined, csrc prefetch) =========
    if (bid == GRID - 1 && tid < NUM_G) g_pcnt[tid] = 0;
    {
        const int sub = lane & 3, grp = lane >> 2;
        int w = gw;
        int dgC = 0, stC = 0, dgN = 0, stN = 0, s0C = 0, s1C = 0;
        if (w < NUM_N) {
            dgC = g_deg[w]; stC = g_woff[w] - dgC;
            if (grp < dgC)     s0C = g_csrc[stC + grp];
            if (grp + 8 < dgC) s1C = g_csrc[stC + grp + 8];
            int wn = w + NWARP;
            if (wn < NUM_N) { dgN = g_deg[wn]; stN = g_woff[wn] - dgN; }
        }
        for (; w < NUM_N; w += NWARP) {
            int wn2 = w + 2 * NWARP;
            int dgN2 = 0, stN2 = 0;
            if (wn2 < NUM_N) { dgN2 = g_deg[wn2]; stN2 = g_woff[wn2] - dgN2; }
            int s0N = 0, s1N = 0;
            if (grp < dgN)     s0N = g_csrc[stN + grp];
            if (grp + 8 < dgN) s1N = g_csrc[stN + grp + 8];
            float ax0=0.f, ay0=0.f, az0=0.f, aw0=0.f;
            float ax1=0.f, ay1=0.f, az1=0.f, aw1=0.f;
            if (grp < dgC)     gather16h(g_h1h, s0C, sub, ax0, ay0, az0, aw0);
            if (grp + 8 < dgC) gather16h(g_h1h, s1C, sub, ax1, ay1, az1, aw1);
            for (int e = grp + 16; e < dgC; e += 16) {
                int s0 = g_csrc[stC + e];
                int s1 = (e + 8 < dgC) ? g_csrc[stC + e + 8] : 0;
                gather16h(g_h1h, s0, sub, ax0, ay0, az0, aw0);
                if (e + 8 < dgC) gather16h(g_h1h, s1, sub, ax1, ay1, az1, aw1);
            }
            float ax = ax0 + ax1, ay = ay0 + ay1, az = az0 + az1, aw = aw0 + aw1;
            #pragma unroll
            for (int o = 4; o < 32; o <<= 1) {
                ax += __shfl_xor_sync(~0u, ax, o);
                ay += __shfl_xor_sync(~0u, ay, o);
                az += __shfl_xor_sync(~0u, az, o);
                aw += __shfl_xor_sync(~0u, aw, o);
            }
            if (lane < 4) {
                float dvd = g_dinv[w];
                float hx=0.f, hy=0.f, hz=0.f, hw=0.f;
                gather16h(g_h1h, w, sub, hx, hy, hz, hw);
                float4 bv = ((const float4*)b1)[sub];
                float ox = fmaxf(fmaf(dvd, ax + hx, bv.x), 0.f) * dvd;
                float oy = fmaxf(fmaf(dvd, ay + hy, bv.y), 0.f) * dvd;
                float oz = fmaxf(fmaf(dvd, az + hz, bv.z), 0.f) * dvd;
                float ow = fmaxf(fmaf(dvd, aw + hw, bv.w), 0.f) * dvd;
                uint2 u;
                *(__half2*)&u.x = __floats2half2_rn(ox, oy);
                *(__half2*)&u.y = __floats2half2_rn(oz, ow);
                ((uint2*)g_qh)[(size_t)w * 4 + sub] = u;
            }
            dgC = dgN; stC = stN; dgN = dgN2; stN = stN2;
            s0C = s0N; s1C = s1N;
        }
    }
    grid_sync(4);

    // ================= P5: prop2 (same pipeline) ===========================
    {
        const int sub = lane & 3, grp = lane >> 2;
        int w = gw;
        int dgC = 0, stC = 0, dgN = 0, stN = 0, s0C = 0, s1C = 0;
        if (w < NUM_N) {
            dgC = g_deg[w]; stC = g_woff[w] - dgC;
            if (grp < dgC)     s0C = g_csrc[stC + grp];
            if (grp + 8 < dgC) s1C = g_csrc[stC + grp + 8];
            int wn = w + NWARP;
            if (wn < NUM_N) { dgN = g_deg[wn]; stN = g_woff[wn] - dgN; }
        }
        for (; w < NUM_N; w += NWARP) {
            int wn2 = w + 2 * NWARP;
            int dgN2 = 0, stN2 = 0;
            if (wn2 < NUM_N) { dgN2 = g_deg[wn2]; stN2 = g_woff[wn2] - dgN2; }
            int s0N = 0, s1N = 0;
            if (grp < dgN)     s0N = g_csrc[stN + grp];
            if (grp + 8 < dgN) s1N = g_csrc[stN + grp + 8];
            float ax0=0.f, ay0=0.f, az0=0.f, aw0=0.f;
            float ax1=0.f, ay1=0.f, az1=0.f, aw1=0.f;
            if (grp < dgC)     gather16h(g_qh, s0C, sub, ax0, ay0, az0, aw0);
            if (grp + 8 < dgC) gather16h(g_qh, s1C, sub, ax1, ay1, az1, aw1);
            for (int e = grp + 16; e < dgC; e += 16) {
                int s0 = g_csrc[stC + e];
                int s1 = (e + 8 < dgC) ? g_csrc[stC + e + 8] : 0;
                gather16h(g_qh, s0, sub, ax0, ay0, az0, aw0);
                if (e + 8 < dgC) gather16h(g_qh, s1, sub, ax1, ay1, az1, aw1);
            }
            float ax = ax0 + ax1, ay = ay0 + ay1, az = az0 + az1, aw = aw0 + aw1;
            #pragma unroll
            for (int o = 4; o < 32; o <<= 1) {
                ax += __shfl_xor_sync(~0u, ax, o);
                ay += __shfl_xor_sync(~0u, ay, o);
                az += __shfl_xor_sync(~0u, az, o);
                aw += __shfl_xor_sync(~0u, aw, o);
            }
            if (lane < 4) {
                float dvd = g_dinv[w];
                float qx=0.f, qy=0.f, qz=0.f, qw=0.f;
                gather16h(g_qh, w, sub, qx, qy, qz, qw);
                float4 o;
                o.x = dvd * (ax + qx); o.y = dvd * (ay + qy);
                o.z = dvd * (az + qz); o.w = dvd * (aw + qw);
                ((float4*)g_r)[(size_t)w * 4 + sub] = o;
            }
            dgC = dgN; stC = stN; dgN = dgN2; stN = stN2;
            s0C = s0N; s1C = s1N;
        }
    }
    grid_sync(5);

    // ================= P6: pool + gemm2 + mlp (blocks 0..127) ==============
    if (bid < NUM_G) {
        for (int i = tid; i < 512; i += TPB) w2s[i] = ((const float4*)W2)[i];
        __syncthreads();
        const int g = bid;
        const int cnt = g_pcnt2[g];
        const int start = g_boff2[g];
        float4 bv = ((const float4*)b2)[lane];
        float4 sum = make_float4(0.f, 0.f, 0.f, 0.f);
        int i = wid;
        float rvN = 0.f;
        if (i < cnt) {
            int n = g_bnode[start + i];
            rvN = (lane < 16) ? g_r[n * 16 + lane] : 0.f;
        }
        for (; i < cnt; i += 32) {
            float rv = rvN;
            int in2 = i + 32;
            if (in2 < cnt) {
                int n2 = g_bnode[start + in2];
                rvN = (lane < 16) ? g_r[n2 * 16 + lane] : 0.f;
            }
            float4 acc = bv;
            #pragma unroll
            for (int k = 0; k < 16; k++) {
                float s = __shfl_sync(~0u, rv, k);
                float4 wv = w2s[k * 32 + lane];
                acc.x = fmaf(s, wv.x, acc.x); acc.y = fmaf(s, wv.y, acc.y);
                acc.z = fmaf(s, wv.z, acc.z); acc.w = fmaf(s, wv.w, acc.w);
            }
            sum.x += fmaxf(acc.x, 0.f); sum.y += fmaxf(acc.y, 0.f);
            sum.z += fmaxf(acc.z, 0.f); sum.w += fmaxf(acc.w, 0.f);
        }
        red[wid * 32 + lane] = sum;
        __syncthreads();
        if (tid < 32) {
            float4 tot = red[tid];
            #pragma unroll
            for (int w2 = 1; w2 < 32; w2++) {
                float4 vv = red[w2 * 32 + tid];
                tot.x += vv.x; tot.y += vv.y; tot.z += vv.z; tot.w += vv.w;
            }
            float inv = 1.f / fmaxf((float)cnt, 1.f);
            ps[tid * 4 + 0] = tot.x * inv; ps[tid * 4 + 1] = tot.y * inv;
            ps[tid * 4 + 2] = tot.z * inv; ps[tid * 4 + 3] = tot.w * inv;
        }
        __syncthreads();
        if (tid < 128) {
            float acc = Lb1[tid];
            #pragma unroll 8
            for (int k = 0; k < 128; k++) acc = fmaf(ps[k], LW1[k * 128 + tid], acc);
            z1[tid] = fmaxf(acc, 0.f);
        }
        __syncthreads();
        if (tid < 2) {
            float a = Lb2[tid];
            for (int k = 0; k < 128; k++) a = fmaf(z1[k], LW2[k * 2 + tid], a);
            z2[tid] = a;
        }
        __syncthreads();
        if (tid == 0) {
            float m = fmaxf(z2[0], z2[1]);
            float lse = m + logf(expf(z2[0] - m) + expf(z2[1] - m));
            out[g * 2 + 0] = z2[0] - lse;
            out[g * 2 + 1] = z2[1] - lse;
        }
    } else {
        for (int i = (bid - NUM_G) * TPB + tid; i < NUM_N; i += (GRID - NUM_G) * TPB)
            g_deg[i] = 0;
    }
}

// -------- launch --------
extern "C" void kernel_launch(void* const* d_in, const int* in_sizes, int n_in,
                              void* d_out, int out_size) {
    const float* x   = (const float*)d_in[0];
    const void*  ei  = d_in[1];
    const void*  bat = d_in[2];
    const float* W1  = (const float*)d_in[3];
    const float* b1  = (const float*)d_in[4];
    const float* W2  = (const float*)d_in[5];
    const float* b2  = (const float*)d_in[6];
    const float* LW1 = (const float*)d_in[7];
    const float* Lb1 = (const float*)d_in[8];
    const float* LW2 = (const float*)d_in[9];
    const float* Lb2 = (const float*)d_in[10];
    float* out = (float*)d_out;

    mega_kernel<<<GRID, TPB>>>(x, ei, bat, W1, b1, W2, b2,
                               LW1, Lb1, LW2, Lb2, out);
}

// round 9
// speedup vs baseline: 1.2733x; 1.2733x over previous
#include <cuda_runtime.h>
#include <cuda_fp16.h>
#include <math.h>

#define NUM_N 100000
#define NUM_E 1600000
#define NUM_G 128
#define D_IN 128

#define GRID  148
#define TPB   1024
#define GT    (GRID * TPB)        // 151552 threads
#define NWARP (GT / 32)           // 4736 warps
#define CHUNK 676                 // 148*676 >= NUM_N
#define NE2   (NUM_E / 2)         // 800000 edge pairs

// -------- device scratch (statics start zeroed) ----------------------------
__device__ int    g_bar[8];
__device__ int    g_batch[NUM_N];
__device__ int    g_deg[NUM_N];      // re-zeroed for replay in P6
__device__ float  g_dinv[NUM_N];
__device__ int    g_woff[NUM_N];     // pristine CSR start offsets
__device__ int    g_erank[NUM_E];    // per-edge rank within dst bucket
__device__ int    g_nrank[NUM_N];    // per-node rank within graph bucket
__device__ int    g_csrc[NUM_E];
__device__ int    g_bsum[GRID];
__device__ int    g_pcnt[NUM_G];     // re-zeroed in P4
__device__ int    g_pcnt2[NUM_G];    // pristine copy for pool
__device__ int    g_boff[NUM_G];     // pristine batch CSR offsets
__device__ int    g_bnode[NUM_N];
__device__ __half g_h1h[NUM_N * 16];
__device__ __half g_qh [NUM_N * 16];
__device__ float  g_r  [NUM_N * 16];

// -------- software grid barrier -------------------------------------------
__device__ __forceinline__ void grid_sync(int j) {
    __syncthreads();
    __threadfence();
    if (threadIdx.x == 0) {
        if (atomicAdd(&g_bar[j], 1) == GRID - 1) {
            atomicExch(&g_bar[(j + 4) % 6], 0);
        } else {
            while (*((volatile int*)&g_bar[j]) < GRID) { }
        }
    }
    __syncthreads();
    __threadfence();
}

__device__ __forceinline__ void gather16h(const __half* base, int s, int sub,
                                          float& ax, float& ay, float& az, float& aw) {
    uint2 u = ((const uint2*)(base))[s * 4 + sub];
    float2 f0 = __half22float2(*(__half2*)&u.x);
    float2 f1 = __half22float2(*(__half2*)&u.y);
    ax += f0.x; ay += f0.y; az += f1.x; aw += f1.y;
}

__global__ __launch_bounds__(TPB, 1) void mega_kernel(
    const float* __restrict__ x, const void* ei, const void* bat,
    const float* __restrict__ W1, const float* __restrict__ b1,
    const float* __restrict__ W2, const float* __restrict__ b2,
    const float* __restrict__ LW1, const float* __restrict__ Lb1,
    const float* __restrict__ LW2, const float* __restrict__ Lb2,
    float* __restrict__ out)
{
    __shared__ float4 w1s[512];
    __shared__ float4 w2s[512];
    __shared__ float4 red[1024];
    __shared__ int    wsum[32];
    __shared__ int    s_i32, s_base;
    __shared__ float  ps[128], z1[128], z2[2];

    const int tid  = threadIdx.x, bid = blockIdx.x;
    const int lane = tid & 31,    wid = tid >> 5;
    const int gth  = bid * TPB + tid;
    const int gw   = gth >> 5;

    // ---- detect int64 vs int32 index layout ----
    if (tid == 0) s_i32 = 0;
    __syncthreads();
    if (tid < 64) {
        long long v = ((const long long*)ei)[(size_t)tid * (NUM_E / 64)];
        if (v < 0 || v >= (long long)NUM_N) s_i32 = 1;
    }
    __syncthreads();
    const bool f64 = (s_i32 == 0);

    // ================= P0: histograms + rank capture =======================
    for (int i = gth; i < NE2; i += GT) {
        int d0, d1;
        if (f64) { int4 v = ((const int4*)ei)[NE2 + i]; d0 = v.x; d1 = v.z; }
        else     { int2 v = ((const int2*)ei)[NE2 + i]; d0 = v.x; d1 = v.y; }
        int r0 = atomicAdd(&g_deg[d0], 1);
        int r1 = atomicAdd(&g_deg[d1], 1);
        ((int2*)g_erank)[i] = make_int2(r0, r1);
    }
    for (int i = gth; i < NUM_N; i += GT) {
        int b = f64 ? (int)((const long long*)bat)[i] : ((const int*)bat)[i];
        g_batch[i] = b;
        g_nrank[i] = atomicAdd(&g_pcnt[b], 1);
    }
    grid_sync(0);

    // ================= P1: block-local scan of deg (+dinv, batch scan) =====
    const int node = bid * CHUNK + tid;
    const bool nvalid = (tid < CHUNK) && (node < NUM_N);
    int deg = nvalid ? g_deg[node] : 0;
    int v = deg;
    #pragma unroll
    for (int o = 1; o < 32; o <<= 1) {
        int n = __shfl_up_sync(~0u, v, o);
        if (lane >= o) v += n;
    }
    if (lane == 31) wsum[wid] = v;
    __syncthreads();
    if (wid == 0) {
        int wv = wsum[lane];
        #pragma unroll
        for (int o = 1; o < 32; o <<= 1) {
            int n = __shfl_up_sync(~0u, wv, o);
            if (lane >= o) wv += n;
        }
        wsum[lane] = wv;
    }
    __syncthreads();
    const int ex_local = (wid ? wsum[wid - 1] : 0) + v - deg;
    if (tid == 0) g_bsum[bid] = wsum[31];
    if (nvalid) g_dinv[node] = rsqrtf((float)deg + 1.f);
    if (bid == 0 && wid == 31) {
        int p0 = g_pcnt[lane*4+0], p1 = g_pcnt[lane*4+1];
        int p2 = g_pcnt[lane*4+2], p3 = g_pcnt[lane*4+3];
        int t1 = p0 + p1, t2 = t1 + p2, t3 = t2 + p3;
        int vv = t3;
        #pragma unroll
        for (int o = 1; o < 32; o <<= 1) {
            int n = __shfl_up_sync(~0u, vv, o);
            if (lane >= o) vv += n;
        }
        int exb = vv - t3;
        g_boff[lane*4+0] = exb;
        g_boff[lane*4+1] = exb + p0;
        g_boff[lane*4+2] = exb + t1;
        g_boff[lane*4+3] = exb + t2;
        g_pcnt2[lane*4+0] = p0; g_pcnt2[lane*4+1] = p1;
        g_pcnt2[lane*4+2] = p2; g_pcnt2[lane*4+3] = p3;
    }
    grid_sync(1);

    // ================= P2: per-block global base, write woff ===============
    if (wid == 0) {
        int s = 0;
        for (int i = lane; i < bid; i += 32) s += g_bsum[i];
        #pragma unroll
        for (int o = 16; o; o >>= 1) s += __shfl_xor_sync(~0u, s, o);
        if (lane == 0) s_base = s;
    }
    __syncthreads();
    if (nvalid) g_woff[node] = s_base + ex_local;
    grid_sync(2);

    // ================= P3: atomic-free scatter + bnode + gemm1 =============
    for (int i = gth; i < NE2; i += GT) {
        int s0, s1, d0, d1;
        if (f64) {
            int4 sv = ((const int4*)ei)[i];       s0 = sv.x; s1 = sv.z;
            int4 dv = ((const int4*)ei)[NE2 + i]; d0 = dv.x; d1 = dv.z;
        } else {
            int2 sv = ((const int2*)ei)[i];       s0 = sv.x; s1 = sv.y;
            int2 dv = ((const int2*)ei)[NE2 + i]; d0 = dv.x; d1 = dv.y;
        }
        int2 rk = ((const int2*)g_erank)[i];
        g_csrc[g_woff[d0] + rk.x] = s0;
        g_csrc[g_woff[d1] + rk.y] = s1;
    }
    for (int i = gth; i < NUM_N; i += GT) {
        g_bnode[g_boff[g_batch[i]] + g_nrank[i]] = i;
    }
    for (int i = tid; i < 512; i += TPB) w1s[i] = ((const float4*)W1)[i];
    __syncthreads();
    {   // gemm1, double-buffered x row, fp16 output (dinv fused) — R7 version
        int w = gw;
        float4 xv = make_float4(0.f, 0.f, 0.f, 0.f);
        if (w < NUM_N) xv = ((const float4*)x)[(size_t)w * 32 + lane];
        for (; w < NUM_N; w += NWARP) {
            int wn = w + NWARP;
            float4 xvN = make_float4(0.f, 0.f, 0.f, 0.f);
            if (wn < NUM_N) xvN = ((const float4*)x)[(size_t)wn * 32 + lane];
            float dvd = g_dinv[w];
            float a[16];
            #pragma unroll
            for (int j = 0; j < 16; j++) a[j] = 0.f;
            {
                float xs[4] = {xv.x, xv.y, xv.z, xv.w};
                int kb4 = lane * 16;
                #pragma unroll
                for (int kk = 0; kk < 4; kk++) {
                    float c = xs[kk];
                    #pragma unroll
                    for (int q = 0; q < 4; q++) {
                        float4 wv = w1s[kb4 + kk * 4 + q];
                        a[q*4+0] = fmaf(c, wv.x, a[q*4+0]);
                        a[q*4+1] = fmaf(c, wv.y, a[q*4+1]);
                        a[q*4+2] = fmaf(c, wv.z, a[q*4+2]);
                        a[q*4+3] = fmaf(c, wv.w, a[q*4+3]);
                    }
                }
            }
            {   // halving butterfly
                float t[16];
                #pragma unroll
                for (int i = 0; i < 16; i++) t[i] = __shfl_xor_sync(~0u, a[i], 16);
                if ((lane & 16) == 0) {
                    #pragma unroll
                    for (int i = 0; i < 8; i++) a[i] += t[i]; }
                else {
                    #pragma unroll
                    for (int i = 0; i < 8; i++) a[i] = a[i+8] + t[i+8]; }
            }
            {
                float t[8];
                #pragma unroll
                for (int i = 0; i < 8; i++) t[i] = __shfl_xor_sync(~0u, a[i], 8);
                if ((lane & 8) == 0) {
                    #pragma unroll
                    for (int i = 0; i < 4; i++) a[i] += t[i]; }
                else {
                    #pragma unroll
                    for (int i = 0; i < 4; i++) a[i] = a[i+4] + t[i+4]; }
            }
            {
                float t[4];
                #pragma unroll
                for (int i = 0; i < 4; i++) t[i] = __shfl_xor_sync(~0u, a[i], 4);
                if ((lane & 4) == 0) { a[0] += t[0]; a[1] += t[1]; }
                else                 { a[0] = a[2] + t[2]; a[1] = a[3] + t[3]; }
            }
            {
                float t0 = __shfl_xor_sync(~0u, a[0], 2);
                float t1 = __shfl_xor_sync(~0u, a[1], 2);
                if ((lane & 2) == 0) a[0] += t0; else a[0] = a[1] + t1;
            }
            a[0] += __shfl_xor_sync(~0u, a[0], 1);
            float vres = a[0] * dvd;
            float vhi = __shfl_down_sync(~0u, vres, 2);
            if ((lane & 3) == 0)
                ((__half2*)g_h1h)[(size_t)w * 8 + (lane >> 2)] =
                    __floats2half2_rn(vres, vhi);
            xv = xvN;
        }
    }
    grid_sync(3);

    // ================= P4: prop1 (fp16 gathers, pipelined meta) ============
    if (bid == GRID - 1 && tid < NUM_G) g_pcnt[tid] = 0;
    {
        const int sub = lane & 3, grp = lane >> 2;
        int w = gw;
        int dgC = 0, stC = 0;
        if (w < NUM_N) { dgC = g_deg[w]; stC = g_woff[w]; }
        for (; w < NUM_N; w += NWARP) {
            int wn = w + NWARP;
            int dgN = 0, stN = 0;
            if (wn < NUM_N) { dgN = g_deg[wn]; stN = g_woff[wn]; }
            float ax0=0.f, ay0=0.f, az0=0.f, aw0=0.f;
            float ax1=0.f, ay1=0.f, az1=0.f, aw1=0.f;
            for (int e = grp; e < dgC; e += 16) {
                int e1 = e + 8;
                bool pr = (e1 < dgC);
                int s0 = g_csrc[stC + e];
                int s1 = pr ? g_csrc[stC + e1] : 0;
                gather16h(g_h1h, s0, sub, ax0, ay0, az0, aw0);
                if (pr) gather16h(g_h1h, s1, sub, ax1, ay1, az1, aw1);
            }
            float ax = ax0 + ax1, ay = ay0 + ay1, az = az0 + az1, aw = aw0 + aw1;
            #pragma unroll
            for (int o = 4; o < 32; o <<= 1) {
                ax += __shfl_xor_sync(~0u, ax, o);
                ay += __shfl_xor_sync(~0u, ay, o);
                az += __shfl_xor_sync(~0u, az, o);
                aw += __shfl_xor_sync(~0u, aw, o);
            }
            if (lane < 4) {
                float dvd = g_dinv[w];
                float hx=0.f, hy=0.f, hz=0.f, hw=0.f;
                gather16h(g_h1h, w, sub, hx, hy, hz, hw);
                float4 bv = ((const float4*)b1)[sub];
                float ox = fmaxf(fmaf(dvd, ax + hx, bv.x), 0.f) * dvd;
                float oy = fmaxf(fmaf(dvd, ay + hy, bv.y), 0.f) * dvd;
                float oz = fmaxf(fmaf(dvd, az + hz, bv.z), 0.f) * dvd;
                float ow = fmaxf(fmaf(dvd, aw + hw, bv.w), 0.f) * dvd;
                uint2 u;
                *(__half2*)&u.x = __floats2half2_rn(ox, oy);
                *(__half2*)&u.y = __floats2half2_rn(oz, ow);
                ((uint2*)g_qh)[(size_t)w * 4 + sub] = u;
            }
            dgC = dgN; stC = stN;
        }
    }
    grid_sync(4);

    // ================= P5: prop2 (fp16 gathers) ============================
    {
        const int sub = lane & 3, grp = lane >> 2;
        int w = gw;
        int dgC = 0, stC = 0;
        if (w < NUM_N) { dgC = g_deg[w]; stC = g_woff[w]; }
        for (; w < NUM_N; w += NWARP) {
            int wn = w + NWARP;
            int dgN = 0, stN = 0;
            if (wn < NUM_N) { dgN = g_deg[wn]; stN = g_woff[wn]; }
            float ax0=0.f, ay0=0.f, az0=0.f, aw0=0.f;
            float ax1=0.f, ay1=0.f, az1=0.f, aw1=0.f;
            for (int e = grp; e < dgC; e += 16) {
                int e1 = e + 8;
                bool pr = (e1 < dgC);
                int s0 = g_csrc[stC + e];
                int s1 = pr ? g_csrc[stC + e1] : 0;
                gather16h(g_qh, s0, sub, ax0, ay0, az0, aw0);
                if (pr) gather16h(g_qh, s1, sub, ax1, ay1, az1, aw1);
            }
            float ax = ax0 + ax1, ay = ay0 + ay1, az = az0 + az1, aw = aw0 + aw1;
            #pragma unroll
            for (int o = 4; o < 32; o <<= 1) {
                ax += __shfl_xor_sync(~0u, ax, o);
                ay += __shfl_xor_sync(~0u, ay, o);
                az += __shfl_xor_sync(~0u, az, o);
                aw += __shfl_xor_sync(~0u, aw, o);
            }
            if (lane < 4) {
                float dvd = g_dinv[w];
                float qx=0.f, qy=0.f, qz=0.f, qw=0.f;
                gather16h(g_qh, w, sub, qx, qy, qz, qw);
                float4 o;
                o.x = dvd * (ax + qx); o.y = dvd * (ay + qy);
                o.z = dvd * (az + qz); o.w = dvd * (aw + qw);
                ((float4*)g_r)[(size_t)w * 4 + sub] = o;
            }
            dgC = dgN; stC = stN;
        }
    }
    grid_sync(5);

    // ================= P6: pool + gemm2 + mlp (blocks 0..127) ==============
    if (bid < NUM_G) {
        for (int i = tid; i < 512; i += TPB) w2s[i] = ((const float4*)W2)[i];
        __syncthreads();
        const int g = bid;
        const int cnt = g_pcnt2[g];
        const int start = g_boff[g];
        float4 bv = ((const float4*)b2)[lane];
        float4 sum = make_float4(0.f, 0.f, 0.f, 0.f);
        int i = wid;
        float rvN = 0.f;
        if (i < cnt) {
            int n = g_bnode[start + i];
            rvN = (lane < 16) ? g_r[n * 16 + lane] : 0.f;
        }
        for (; i < cnt; i += 32) {
            float rv = rvN;
            int in2 = i + 32;
            if (in2 < cnt) {
                int n2 = g_bnode[start + in2];
                rvN = (lane < 16) ? g_r[n2 * 16 + lane] : 0.f;
            }
            float4 acc = bv;
            #pragma unroll
            for (int k = 0; k < 16; k++) {
                float s = __shfl_sync(~0u, rv, k);
                float4 wv = w2s[k * 32 + lane];
                acc.x = fmaf(s, wv.x, acc.x); acc.y = fmaf(s, wv.y, acc.y);
                acc.z = fmaf(s, wv.z, acc.z); acc.w = fmaf(s, wv.w, acc.w);
            }
            sum.x += fmaxf(acc.x, 0.f); sum.y += fmaxf(acc.y, 0.f);
            sum.z += fmaxf(acc.z, 0.f); sum.w += fmaxf(acc.w, 0.f);
        }
        red[wid * 32 + lane] = sum;
        __syncthreads();
        if (tid < 32) {
            float4 tot = red[tid];
            #pragma unroll
            for (int w2 = 1; w2 < 32; w2++) {
                float4 vv = red[w2 * 32 + tid];
                tot.x += vv.x; tot.y += vv.y; tot.z += vv.z; tot.w += vv.w;
            }
            float inv = 1.f / fmaxf((float)cnt, 1.f);
            ps[tid * 4 + 0] = tot.x * inv; ps[tid * 4 + 1] = tot.y * inv;
            ps[tid * 4 + 2] = tot.z * inv; ps[tid * 4 + 3] = tot.w * inv;
        }
        __syncthreads();
        if (tid < 128) {
            float acc = Lb1[tid];
            #pragma unroll 8
            for (int k = 0; k < 128; k++) acc = fmaf(ps[k], LW1[k * 128 + tid], acc);
            z1[tid] = fmaxf(acc, 0.f);
        }
        __syncthreads();
        if (tid < 2) {
            float a = Lb2[tid];
            for (int k = 0; k < 128; k++) a = fmaf(z1[k], LW2[k * 2 + tid], a);
            z2[tid] = a;
        }
        __syncthreads();
        if (tid == 0) {
            float m = fmaxf(z2[0], z2[1]);
            float lse = m + logf(expf(z2[0] - m) + expf(z2[1] - m));
            out[g * 2 + 0] = z2[0] - lse;
            out[g * 2 + 1] = z2[1] - lse;
        }
    } else {
        for (int i = (bid - NUM_G) * TPB + tid; i < NUM_N; i += (GRID - NUM_G) * TPB)
            g_deg[i] = 0;
    }
}

// -------- launch --------
extern "C" void kernel_launch(void* const* d_in, const int* in_sizes, int n_in,
                              void* d_out, int out_size) {
    const float* x   = (const float*)d_in[0];
    const void*  ei  = d_in[1];
    const void*  bat = d_in[2];
    const float* W1  = (const float*)d_in[3];
    const float* b1  = (const float*)d_in[4];
    const float* W2  = (const float*)d_in[5];
    const float* b2  = (const float*)d_in[6];
    const float* LW1 = (const float*)d_in[7];
    const float* Lb1 = (const float*)d_in[8];
    const float* LW2 = (const float*)d_in[9];
    const float* Lb2 = (const float*)d_in[10];
    float* out = (float*)d_out;

    mega_kernel<<<GRID, TPB>>>(x, ei, bat, W1, b1, W2, b2,
                               LW1, Lb1, LW2, Lb2, out);
}

// round 10
// speedup vs baseline: 1.2889x; 1.0123x over previous
#include <cuda_runtime.h>
#include <cuda_fp16.h>
#include <math.h>

#define NUM_N 100000
#define NUM_E 1600000
#define NUM_G 128
#define D_IN 128

#define GRID  148
#define TPB   1024
#define GT    (GRID * TPB)        // 151552 threads
#define NWARP (GT / 32)           // 4736 warps
#define CHUNK 676                 // 148*676 >= NUM_N
#define NE2   (NUM_E / 2)         // 800000 edge pairs

// -------- device scratch (statics start zeroed) ----------------------------
__device__ int    g_bar[8];
__device__ int    g_batch[NUM_N];
__device__ int    g_deg[NUM_N];      // re-zeroed for replay in P6
__device__ float  g_dinv[NUM_N];
__device__ int    g_woff[NUM_N];     // pristine CSR start offsets
__device__ int    g_erank[NUM_E];    // per-edge rank within dst bucket
__device__ int    g_nrank[NUM_N];    // per-node rank within graph bucket
__device__ int    g_csrc[NUM_E];
__device__ int    g_bsum[GRID];
__device__ int    g_pcnt[NUM_G];     // re-zeroed in P4
__device__ int    g_pcnt2[NUM_G];    // pristine copy for pool
__device__ int    g_boff[NUM_G];     // pristine batch CSR offsets
__device__ int    g_bnode[NUM_N];
__device__ __half g_h1h[NUM_N * 16];
__device__ __half g_qh [NUM_N * 16];
__device__ float  g_r  [NUM_N * 16];

// -------- software grid barrier -------------------------------------------
__device__ __forceinline__ void grid_sync(int j) {
    __syncthreads();
    __threadfence();
    if (threadIdx.x == 0) {
        if (atomicAdd(&g_bar[j], 1) == GRID - 1) {
            atomicExch(&g_bar[(j + 4) % 6], 0);
        } else {
            while (*((volatile int*)&g_bar[j]) < GRID) { }
        }
    }
    __syncthreads();
    __threadfence();
}

// fp16 gather + HADD2 accumulate (2 ops per row chunk instead of 6)
__device__ __forceinline__ void gatherh2(const __half* base, int s, int sub,
                                         __half2& a0, __half2& a1) {
    uint2 u = ((const uint2*)(base))[s * 4 + sub];
    a0 = __hadd2(a0, *(__half2*)&u.x);
    a1 = __hadd2(a1, *(__half2*)&u.y);
}

// fp32 read of one node's 4-half chunk
__device__ __forceinline__ void read16h(const __half* base, int s, int sub,
                                        float& x0, float& y0, float& z0, float& w0) {
    uint2 u = ((const uint2*)(base))[s * 4 + sub];
    float2 f0 = __half22float2(*(__half2*)&u.x);
    float2 f1 = __half22float2(*(__half2*)&u.y);
    x0 = f0.x; y0 = f0.y; z0 = f1.x; w0 = f1.y;
}

__global__ __launch_bounds__(TPB, 1) void mega_kernel(
    const float* __restrict__ x, const void* ei, const void* bat,
    const float* __restrict__ W1, const float* __restrict__ b1,
    const float* __restrict__ W2, const float* __restrict__ b2,
    const float* __restrict__ LW1, const float* __restrict__ Lb1,
    const float* __restrict__ LW2, const float* __restrict__ Lb2,
    float* __restrict__ out)
{
    __shared__ float4 w1s[512];
    __shared__ float4 w2s[512];
    __shared__ float4 red[1024];
    __shared__ int    wsum[32];
    __shared__ int    s_i32, s_base;
    __shared__ float  ps[128], z1[128], z2[2];

    const int tid  = threadIdx.x, bid = blockIdx.x;
    const int lane = tid & 31,    wid = tid >> 5;
    const int gth  = bid * TPB + tid;
    const int gw   = gth >> 5;

    // ---- detect int64 vs int32 index layout ----
    if (tid == 0) s_i32 = 0;
    __syncthreads();
    if (tid < 64) {
        long long v = ((const long long*)ei)[(size_t)tid * (NUM_E / 64)];
        if (v < 0 || v >= (long long)NUM_N) s_i32 = 1;
    }
    __syncthreads();
    const bool f64 = (s_i32 == 0);

    // ================= P0: histograms + rank capture =======================
    for (int i = gth; i < NE2; i += GT) {
        int d0, d1;
        if (f64) { int4 v = ((const int4*)ei)[NE2 + i]; d0 = v.x; d1 = v.z; }
        else     { int2 v = ((const int2*)ei)[NE2 + i]; d0 = v.x; d1 = v.y; }
        int r0 = atomicAdd(&g_deg[d0], 1);
        int r1 = atomicAdd(&g_deg[d1], 1);
        ((int2*)g_erank)[i] = make_int2(r0, r1);
    }
    for (int i = gth; i < NUM_N; i += GT) {
        int b = f64 ? (int)((const long long*)bat)[i] : ((const int*)bat)[i];
        g_batch[i] = b;
        g_nrank[i] = atomicAdd(&g_pcnt[b], 1);
    }
    grid_sync(0);

    // ================= P1: block-local scan of deg (+dinv, batch scan) =====
    const int node = bid * CHUNK + tid;
    const bool nvalid = (tid < CHUNK) && (node < NUM_N);
    int deg = nvalid ? g_deg[node] : 0;
    int v = deg;
    #pragma unroll
    for (int o = 1; o < 32; o <<= 1) {
        int n = __shfl_up_sync(~0u, v, o);
        if (lane >= o) v += n;
    }
    if (lane == 31) wsum[wid] = v;
    __syncthreads();
    if (wid == 0) {
        int wv = wsum[lane];
        #pragma unroll
        for (int o = 1; o < 32; o <<= 1) {
            int n = __shfl_up_sync(~0u, wv, o);
            if (lane >= o) wv += n;
        }
        wsum[lane] = wv;
    }
    __syncthreads();
    const int ex_local = (wid ? wsum[wid - 1] : 0) + v - deg;
    if (tid == 0) g_bsum[bid] = wsum[31];
    if (nvalid) g_dinv[node] = rsqrtf((float)deg + 1.f);
    if (bid == 0 && wid == 31) {
        int p0 = g_pcnt[lane*4+0], p1 = g_pcnt[lane*4+1];
        int p2 = g_pcnt[lane*4+2], p3 = g_pcnt[lane*4+3];
        int t1 = p0 + p1, t2 = t1 + p2, t3 = t2 + p3;
        int vv = t3;
        #pragma unroll
        for (int o = 1; o < 32; o <<= 1) {
            int n = __shfl_up_sync(~0u, vv, o);
            if (lane >= o) vv += n;
        }
        int exb = vv - t3;
        g_boff[lane*4+0] = exb;
        g_boff[lane*4+1] = exb + p0;
        g_boff[lane*4+2] = exb + t1;
        g_boff[lane*4+3] = exb + t2;
        g_pcnt2[lane*4+0] = p0; g_pcnt2[lane*4+1] = p1;
        g_pcnt2[lane*4+2] = p2; g_pcnt2[lane*4+3] = p3;
    }
    grid_sync(1);

    // ================= P2: per-block global base, write woff ===============
    if (wid == 0) {
        int s = 0;
        for (int i = lane; i < bid; i += 32) s += g_bsum[i];
        #pragma unroll
        for (int o = 16; o; o >>= 1) s += __shfl_xor_sync(~0u, s, o);
        if (lane == 0) s_base = s;
    }
    __syncthreads();
    if (nvalid) g_woff[node] = s_base + ex_local;
    grid_sync(2);

    // ================= P3: atomic-free scatter + bnode + gemm1 =============
    for (int i = gth; i < NE2; i += GT) {
        int s0, s1, d0, d1;
        if (f64) {
            int4 sv = ((const int4*)ei)[i];       s0 = sv.x; s1 = sv.z;
            int4 dv = ((const int4*)ei)[NE2 + i]; d0 = dv.x; d1 = dv.z;
        } else {
            int2 sv = ((const int2*)ei)[i];       s0 = sv.x; s1 = sv.y;
            int2 dv = ((const int2*)ei)[NE2 + i]; d0 = dv.x; d1 = dv.y;
        }
        int2 rk = ((const int2*)g_erank)[i];
        g_csrc[g_woff[d0] + rk.x] = s0;
        g_csrc[g_woff[d1] + rk.y] = s1;
    }
    for (int i = gth; i < NUM_N; i += GT) {
        g_bnode[g_boff[g_batch[i]] + g_nrank[i]] = i;
    }
    for (int i = tid; i < 512; i += TPB) w1s[i] = ((const float4*)W1)[i];
    __syncthreads();
    {   // gemm1, double-buffered x row, fp16 output (dinv fused)
        int w = gw;
        float4 xv = make_float4(0.f, 0.f, 0.f, 0.f);
        if (w < NUM_N) xv = ((const float4*)x)[(size_t)w * 32 + lane];
        for (; w < NUM_N; w += NWARP) {
            int wn = w + NWARP;
            float4 xvN = make_float4(0.f, 0.f, 0.f, 0.f);
            if (wn < NUM_N) xvN = ((const float4*)x)[(size_t)wn * 32 + lane];
            float dvd = g_dinv[w];
            float a[16];
            #pragma unroll
            for (int j = 0; j < 16; j++) a[j] = 0.f;
            {
                float xs[4] = {xv.x, xv.y, xv.z, xv.w};
                int kb4 = lane * 16;
                #pragma unroll
                for (int kk = 0; kk < 4; kk++) {
                    float c = xs[kk];
                    #pragma unroll
                    for (int q = 0; q < 4; q++) {
                        float4 wv = w1s[kb4 + kk * 4 + q];
                        a[q*4+0] = fmaf(c, wv.x, a[q*4+0]);
                        a[q*4+1] = fmaf(c, wv.y, a[q*4+1]);
                        a[q*4+2] = fmaf(c, wv.z, a[q*4+2]);
                        a[q*4+3] = fmaf(c, wv.w, a[q*4+3]);
                    }
                }
            }
            {   // halving butterfly
                float t[16];
                #pragma unroll
                for (int i = 0; i < 16; i++) t[i] = __shfl_xor_sync(~0u, a[i], 16);
                if ((lane & 16) == 0) {
                    #pragma unroll
                    for (int i = 0; i < 8; i++) a[i] += t[i]; }
                else {
                    #pragma unroll
                    for (int i = 0; i < 8; i++) a[i] = a[i+8] + t[i+8]; }
            }
            {
                float t[8];
                #pragma unroll
                for (int i = 0; i < 8; i++) t[i] = __shfl_xor_sync(~0u, a[i], 8);
                if ((lane & 8) == 0) {
                    #pragma unroll
                    for (int i = 0; i < 4; i++) a[i] += t[i]; }
                else {
                    #pragma unroll
                    for (int i = 0; i < 4; i++) a[i] = a[i+4] + t[i+4]; }
            }
            {
                float t[4];
                #pragma unroll
                for (int i = 0; i < 4; i++) t[i] = __shfl_xor_sync(~0u, a[i], 4);
                if ((lane & 4) == 0) { a[0] += t[0]; a[1] += t[1]; }
                else                 { a[0] = a[2] + t[2]; a[1] = a[3] + t[3]; }
            }
            {
                float t0 = __shfl_xor_sync(~0u, a[0], 2);
                float t1 = __shfl_xor_sync(~0u, a[1], 2);
                if ((lane & 2) == 0) a[0] += t0; else a[0] = a[1] + t1;
            }
            a[0] += __shfl_xor_sync(~0u, a[0], 1);
            float vres = a[0] * dvd;
            float vhi = __shfl_down_sync(~0u, vres, 2);
            if ((lane & 3) == 0)
                ((__half2*)g_h1h)[(size_t)w * 8 + (lane >> 2)] =
                    __floats2half2_rn(vres, vhi);
            xv = xvN;
        }
    }
    grid_sync(3);

    // ================= P4: prop1 (HADD2 accumulation) ======================
    if (bid == GRID - 1 && tid < NUM_G) g_pcnt[tid] = 0;
    {
        const int sub = lane & 3, grp = lane >> 2;
        const __half2 h2z = __floats2half2_rn(0.f, 0.f);
        int w = gw;
        int dgC = 0, stC = 0;
        if (w < NUM_N) { dgC = g_deg[w]; stC = g_woff[w]; }
        for (; w < NUM_N; w += NWARP) {
            int wn = w + NWARP;
            int dgN = 0, stN = 0;
            if (wn < NUM_N) { dgN = g_deg[wn]; stN = g_woff[wn]; }
            __half2 p0 = h2z, p1 = h2z, q0 = h2z, q1 = h2z;
            for (int e = grp; e < dgC; e += 16) {
                int e1 = e + 8;
                bool pr = (e1 < dgC);
                int s0 = g_csrc[stC + e];
                int s1 = pr ? g_csrc[stC + e1] : 0;
                gatherh2(g_h1h, s0, sub, p0, p1);
                if (pr) gatherh2(g_h1h, s1, sub, q0, q1);
            }
            float2 fp0 = __half22float2(p0), fp1 = __half22float2(p1);
            float2 fq0 = __half22float2(q0), fq1 = __half22float2(q1);
            float ax = fp0.x + fq0.x, ay = fp0.y + fq0.y;
            float az = fp1.x + fq1.x, aw = fp1.y + fq1.y;
            #pragma unroll
            for (int o = 4; o < 32; o <<= 1) {
                ax += __shfl_xor_sync(~0u, ax, o);
                ay += __shfl_xor_sync(~0u, ay, o);
                az += __shfl_xor_sync(~0u, az, o);
                aw += __shfl_xor_sync(~0u, aw, o);
            }
            if (lane < 4) {
                float dvd = g_dinv[w];
                float hx, hy, hz, hw;
                read16h(g_h1h, w, sub, hx, hy, hz, hw);
                float4 bv = ((const float4*)b1)[sub];
                float ox = fmaxf(fmaf(dvd, ax + hx, bv.x), 0.f) * dvd;
                float oy = fmaxf(fmaf(dvd, ay + hy, bv.y), 0.f) * dvd;
                float oz = fmaxf(fmaf(dvd, az + hz, bv.z), 0.f) * dvd;
                float ow = fmaxf(fmaf(dvd, aw + hw, bv.w), 0.f) * dvd;
                uint2 u;
                *(__half2*)&u.x = __floats2half2_rn(ox, oy);
                *(__half2*)&u.y = __floats2half2_rn(oz, ow);
                ((uint2*)g_qh)[(size_t)w * 4 + sub] = u;
            }
            dgC = dgN; stC = stN;
        }
    }
    grid_sync(4);

    // ================= P5: prop2 (HADD2 accumulation) ======================
    {
        const int sub = lane & 3, grp = lane >> 2;
        const __half2 h2z = __floats2half2_rn(0.f, 0.f);
        int w = gw;
        int dgC = 0, stC = 0;
        if (w < NUM_N) { dgC = g_deg[w]; stC = g_woff[w]; }
        for (; w < NUM_N; w += NWARP) {
            int wn = w + NWARP;
            int dgN = 0, stN = 0;
            if (wn < NUM_N) { dgN = g_deg[wn]; stN = g_woff[wn]; }
            __half2 p0 = h2z, p1 = h2z, q0 = h2z, q1 = h2z;
            for (int e = grp; e < dgC; e += 16) {
                int e1 = e + 8;
                bool pr = (e1 < dgC);
                int s0 = g_csrc[stC + e];
                int s1 = pr ? g_csrc[stC + e1] : 0;
                gatherh2(g_qh, s0, sub, p0, p1);
                if (pr) gatherh2(g_qh, s1, sub, q0, q1);
            }
            float2 fp0 = __half22float2(p0), fp1 = __half22float2(p1);
            float2 fq0 = __half22float2(q0), fq1 = __half22float2(q1);
            float ax = fp0.x + fq0.x, ay = fp0.y + fq0.y;
            float az = fp1.x + fq1.x, aw = fp1.y + fq1.y;
            #pragma unroll
            for (int o = 4; o < 32; o <<= 1) {
                ax += __shfl_xor_sync(~0u, ax, o);
                ay += __shfl_xor_sync(~0u, ay, o);
                az += __shfl_xor_sync(~0u, az, o);
                aw += __shfl_xor_sync(~0u, aw, o);
            }
            if (lane < 4) {
                float dvd = g_dinv[w];
                float qx, qy, qz, qw;
                read16h(g_qh, w, sub, qx, qy, qz, qw);
                float4 o;
                o.x = dvd * (ax + qx); o.y = dvd * (ay + qy);
                o.z = dvd * (az + qz); o.w = dvd * (aw + qw);
                ((float4*)g_r)[(size_t)w * 4 + sub] = o;
            }
            dgC = dgN; stC = stN;
        }
    }
    grid_sync(5);

    // ================= P6: pool + gemm2 + mlp (blocks 0..127) ==============
    if (bid < NUM_G) {
        for (int i = tid; i < 512; i += TPB) w2s[i] = ((const float4*)W2)[i];
        __syncthreads();
        const int g = bid;
        const int cnt = g_pcnt2[g];
        const int start = g_boff[g];
        float4 bv = ((const float4*)b2)[lane];
        float4 sum = make_float4(0.f, 0.f, 0.f, 0.f);
        int i = wid;
        float rvN = 0.f;
        if (i < cnt) {
            int n = g_bnode[start + i];
            rvN = (lane < 16) ? g_r[n * 16 + lane] : 0.f;
        }
        for (; i < cnt; i += 32) {
            float rv = rvN;
            int in2 = i + 32;
            if (in2 < cnt) {
                int n2 = g_bnode[start + in2];
                rvN = (lane < 16) ? g_r[n2 * 16 + lane] : 0.f;
            }
            float4 acc = bv;
            #pragma unroll
            for (int k = 0; k < 16; k++) {
                float s = __shfl_sync(~0u, rv, k);
                float4 wv = w2s[k * 32 + lane];
                acc.x = fmaf(s, wv.x, acc.x); acc.y = fmaf(s, wv.y, acc.y);
                acc.z = fmaf(s, wv.z, acc.z); acc.w = fmaf(s, wv.w, acc.w);
            }
            sum.x += fmaxf(acc.x, 0.f); sum.y += fmaxf(acc.y, 0.f);
            sum.z += fmaxf(acc.z, 0.f); sum.w += fmaxf(acc.w, 0.f);
        }
        red[wid * 32 + lane] = sum;
        __syncthreads();
        if (tid < 32) {
            float4 tot = red[tid];
            #pragma unroll
            for (int w2 = 1; w2 < 32; w2++) {
                float4 vv = red[w2 * 32 + tid];
                tot.x += vv.x; tot.y += vv.y; tot.z += vv.z; tot.w += vv.w;
            }
            float inv = 1.f / fmaxf((float)cnt, 1.f);
            ps[tid * 4 + 0] = tot.x * inv; ps[tid * 4 + 1] = tot.y * inv;
            ps[tid * 4 + 2] = tot.z * inv; ps[tid * 4 + 3] = tot.w * inv;
        }
        __syncthreads();
        if (tid < 128) {
            float acc = Lb1[tid];
            #pragma unroll 8
            for (int k = 0; k < 128; k++) acc = fmaf(ps[k], LW1[k * 128 + tid], acc);
            z1[tid] = fmaxf(acc, 0.f);
        }
        __syncthreads();
        if (tid < 2) {
            float a = Lb2[tid];
            for (int k = 0; k < 128; k++) a = fmaf(z1[k], LW2[k * 2 + tid], a);
            z2[tid] = a;
        }
        __syncthreads();
        if (tid == 0) {
            float m = fmaxf(z2[0], z2[1]);
            float lse = m + logf(expf(z2[0] - m) + expf(z2[1] - m));
            out[g * 2 + 0] = z2[0] - lse;
            out[g * 2 + 1] = z2[1] - lse;
        }
    } else {
        for (int i = (bid - NUM_G) * TPB + tid; i < NUM_N; i += (GRID - NUM_G) * TPB)
            g_deg[i] = 0;
    }
}

// -------- launch --------
extern "C" void kernel_launch(void* const* d_in, const int* in_sizes, int n_in,
                              void* d_out, int out_size) {
    const float* x   = (const float*)d_in[0];
    const void*  ei  = d_in[1];
    const void*  bat = d_in[2];
    const float* W1  = (const float*)d_in[3];
    const float* b1  = (const float*)d_in[4];
    const float* W2  = (const float*)d_in[5];
    const float* b2  = (const float*)d_in[6];
    const float* LW1 = (const float*)d_in[7];
    const float* Lb1 = (const float*)d_in[8];
    const float* LW2 = (const float*)d_in[9];
    const float* Lb2 = (const float*)d_in[10];
    float* out = (float*)d_out;

    mega_kernel<<<GRID, TPB>>>(x, ei, bat, W1, b1, W2, b2,
                               LW1, Lb1, LW2, Lb2, out);
}

// round 11
// speedup vs baseline: 1.3699x; 1.0628x over previous
#include <cuda_runtime.h>
#include <cuda_fp16.h>
#include <math.h>

#define NUM_N 100000
#define NUM_E 1600000
#define NUM_G 128
#define D_IN 128

#define GRID  148
#define TPB   1024
#define GT    (GRID * TPB)        // 151552 threads
#define NWARP (GT / 32)           // 4736 warps
#define CHUNK 676                 // 148*676 >= NUM_N
#define NE2   (NUM_E / 2)         // 800000 edge pairs

// -------- device scratch (statics start zeroed) ----------------------------
__device__ int    g_bar[8];
__device__ int    g_batch[NUM_N];
__device__ int    g_deg[NUM_N];      // re-zeroed for replay in P6
__device__ float  g_dinv[NUM_N];
__device__ int    g_woff[NUM_N];     // pristine CSR start offsets
__device__ int    g_erank[NUM_E];    // per-edge rank within dst bucket
__device__ int    g_nrank[NUM_N];    // per-node rank within graph bucket
__device__ int    g_csrc[NUM_E];
__device__ int    g_bsum[GRID];
__device__ int    g_pcnt[NUM_G];     // re-zeroed in P4
__device__ int    g_pcnt2[NUM_G];    // pristine copy for pool
__device__ int    g_boff[NUM_G];     // pristine batch CSR offsets
__device__ int    g_bnode[NUM_N];
__device__ __half g_h1h[NUM_N * 16];
__device__ __half g_qh [NUM_N * 16];
__device__ float  g_r  [NUM_N * 16];

// -------- software grid barrier -------------------------------------------
__device__ __forceinline__ void grid_sync(int j) {
    __syncthreads();
    __threadfence();
    if (threadIdx.x == 0) {
        if (atomicAdd(&g_bar[j], 1) == GRID - 1) {
            atomicExch(&g_bar[(j + 4) % 6], 0);
        } else {
            while (*((volatile int*)&g_bar[j]) < GRID) { }
        }
    }
    __syncthreads();
    __threadfence();
}

// fp16 gather + HADD2 accumulate
__device__ __forceinline__ void gatherh2(const __half* base, int s, int sub,
                                         __half2& a0, __half2& a1) {
    uint2 u = ((const uint2*)(base))[s * 4 + sub];
    a0 = __hadd2(a0, *(__half2*)&u.x);
    a1 = __hadd2(a1, *(__half2*)&u.y);
}

// fp32 read of one node's 4-half chunk
__device__ __forceinline__ void read16h(const __half* base, int s, int sub,
                                        float& x0, float& y0, float& z0, float& w0) {
    uint2 u = ((const uint2*)(base))[s * 4 + sub];
    float2 f0 = __half22float2(*(__half2*)&u.x);
    float2 f1 = __half22float2(*(__half2*)&u.y);
    x0 = f0.x; y0 = f0.y; z0 = f1.x; w0 = f1.y;
}

// packed f32x2 helpers
__device__ __forceinline__ unsigned long long fma2(unsigned long long c,
                                                   unsigned long long w,
                                                   unsigned long long a) {
    unsigned long long d;
    asm("fma.rn.f32x2 %0, %1, %2, %3;" : "=l"(d) : "l"(c), "l"(w), "l"(a));
    return d;
}
__device__ __forceinline__ unsigned long long pack2(float c) {
    unsigned long long d;
    asm("mov.b64 %0, {%1, %1};" : "=l"(d) : "f"(c));
    return d;
}
__device__ __forceinline__ void unpack2(unsigned long long p, float& lo, float& hi) {
    asm("mov.b64 {%0, %1}, %2;" : "=f"(lo), "=f"(hi) : "l"(p));
}

__global__ __launch_bounds__(TPB, 1) void mega_kernel(
    const float* __restrict__ x, const void* ei, const void* bat,
    const float* __restrict__ W1, const float* __restrict__ b1,
    const float* __restrict__ W2, const float* __restrict__ b2,
    const float* __restrict__ LW1, const float* __restrict__ Lb1,
    const float* __restrict__ LW2, const float* __restrict__ Lb2,
    float* __restrict__ out)
{
    __shared__ ulonglong2 w1s[512];   // W1 as f32x2 pairs
    __shared__ float4 w2s[512];
    __shared__ float4 red[1024];
    __shared__ int    wsum[32];
    __shared__ int    s_i32, s_base;
    __shared__ float  ps[128], z1[128], z2[2];

    const int tid  = threadIdx.x, bid = blockIdx.x;
    const int lane = tid & 31,    wid = tid >> 5;
    const int gth  = bid * TPB + tid;
    const int gw   = gth >> 5;

    // ---- detect int64 vs int32 index layout ----
    if (tid == 0) s_i32 = 0;
    __syncthreads();
    if (tid < 64) {
        long long v = ((const long long*)ei)[(size_t)tid * (NUM_E / 64)];
        if (v < 0 || v >= (long long)NUM_N) s_i32 = 1;
    }
    __syncthreads();
    const bool f64 = (s_i32 == 0);

    // ================= P0: histograms + rank capture =======================
    for (int i = gth; i < NE2; i += GT) {
        int d0, d1;
        if (f64) { int4 v = ((const int4*)ei)[NE2 + i]; d0 = v.x; d1 = v.z; }
        else     { int2 v = ((const int2*)ei)[NE2 + i]; d0 = v.x; d1 = v.y; }
        int r0 = atomicAdd(&g_deg[d0], 1);
        int r1 = atomicAdd(&g_deg[d1], 1);
        ((int2*)g_erank)[i] = make_int2(r0, r1);
    }
    for (int i = gth; i < NUM_N; i += GT) {
        int b = f64 ? (int)((const long long*)bat)[i] : ((const int*)bat)[i];
        g_batch[i] = b;
        g_nrank[i] = atomicAdd(&g_pcnt[b], 1);
    }
    grid_sync(0);

    // ================= P1: block-local scan of deg (+dinv, batch scan) =====
    const int node = bid * CHUNK + tid;
    const bool nvalid = (tid < CHUNK) && (node < NUM_N);
    int deg = nvalid ? g_deg[node] : 0;
    int v = deg;
    #pragma unroll
    for (int o = 1; o < 32; o <<= 1) {
        int n = __shfl_up_sync(~0u, v, o);
        if (lane >= o) v += n;
    }
    if (lane == 31) wsum[wid] = v;
    __syncthreads();
    if (wid == 0) {
        int wv = wsum[lane];
        #pragma unroll
        for (int o = 1; o < 32; o <<= 1) {
            int n = __shfl_up_sync(~0u, wv, o);
            if (lane >= o) wv += n;
        }
        wsum[lane] = wv;
    }
    __syncthreads();
    const int ex_local = (wid ? wsum[wid - 1] : 0) + v - deg;
    if (tid == 0) g_bsum[bid] = wsum[31];
    if (nvalid) g_dinv[node] = rsqrtf((float)deg + 1.f);
    if (bid == 0 && wid == 31) {
        int p0 = g_pcnt[lane*4+0], p1 = g_pcnt[lane*4+1];
        int p2 = g_pcnt[lane*4+2], p3 = g_pcnt[lane*4+3];
        int t1 = p0 + p1, t2 = t1 + p2, t3 = t2 + p3;
        int vv = t3;
        #pragma unroll
        for (int o = 1; o < 32; o <<= 1) {
            int n = __shfl_up_sync(~0u, vv, o);
            if (lane >= o) vv += n;
        }
        int exb = vv - t3;
        g_boff[lane*4+0] = exb;
        g_boff[lane*4+1] = exb + p0;
        g_boff[lane*4+2] = exb + t1;
        g_boff[lane*4+3] = exb + t2;
        g_pcnt2[lane*4+0] = p0; g_pcnt2[lane*4+1] = p1;
        g_pcnt2[lane*4+2] = p2; g_pcnt2[lane*4+3] = p3;
    }
    grid_sync(1);

    // ================= P2: per-block global base, write woff ===============
    if (wid == 0) {
        int s = 0;
        for (int i = lane; i < bid; i += 32) s += g_bsum[i];
        #pragma unroll
        for (int o = 16; o; o >>= 1) s += __shfl_xor_sync(~0u, s, o);
        if (lane == 0) s_base = s;
    }
    __syncthreads();
    if (nvalid) g_woff[node] = s_base + ex_local;
    grid_sync(2);

    // ================= P3: atomic-free scatter (x2 unroll) + bnode + gemm1 =
    for (int i = gth; i < NE2; i += 2 * GT) {
        int s0, s1, d0, d1;
        if (f64) {
            int4 sv = ((const int4*)ei)[i];       s0 = sv.x; s1 = sv.z;
            int4 dv = ((const int4*)ei)[NE2 + i]; d0 = dv.x; d1 = dv.z;
        } else {
            int2 sv = ((const int2*)ei)[i];       s0 = sv.x; s1 = sv.y;
            int2 dv = ((const int2*)ei)[NE2 + i]; d0 = dv.x; d1 = dv.y;
        }
        int2 rkA = ((const int2*)g_erank)[i];
        int i2 = i + GT;
        bool have2 = (i2 < NE2);
        int s2 = 0, s3 = 0, d2 = 0, d3 = 0;
        int2 rkB = make_int2(0, 0);
        if (have2) {
            if (f64) {
                int4 sv = ((const int4*)ei)[i2];       s2 = sv.x; s3 = sv.z;
                int4 dv = ((const int4*)ei)[NE2 + i2]; d2 = dv.x; d3 = dv.z;
            } else {
                int2 sv = ((const int2*)ei)[i2];       s2 = sv.x; s3 = sv.y;
                int2 dv = ((const int2*)ei)[NE2 + i2]; d2 = dv.x; d3 = dv.y;
            }
            rkB = ((const int2*)g_erank)[i2];
        }
        int w0 = g_woff[d0];
        int w1 = g_woff[d1];
        int w2 = have2 ? g_woff[d2] : 0;
        int w3 = have2 ? g_woff[d3] : 0;
        g_csrc[w0 + rkA.x] = s0;
        g_csrc[w1 + rkA.y] = s1;
        if (have2) {
            g_csrc[w2 + rkB.x] = s2;
            g_csrc[w3 + rkB.y] = s3;
        }
    }
    for (int i = gth; i < NUM_N; i += GT) {
        g_bnode[g_boff[g_batch[i]] + g_nrank[i]] = i;
    }
    for (int i = tid; i < 512; i += TPB) w1s[i] = ((const ulonglong2*)W1)[i];
    __syncthreads();
    {   // gemm1: f32x2 packed FMAs, double-buffered x row, fp16 output
        int w = gw;
        float4 xv = make_float4(0.f, 0.f, 0.f, 0.f);
        if (w < NUM_N) xv = ((const float4*)x)[(size_t)w * 32 + lane];
        for (; w < NUM_N; w += NWARP) {
            int wn = w + NWARP;
            float4 xvN = make_float4(0.f, 0.f, 0.f, 0.f);
            if (wn < NUM_N) xvN = ((const float4*)x)[(size_t)wn * 32 + lane];
            float dvd = g_dinv[w];
            unsigned long long A[8];
            #pragma unroll
            for (int j = 0; j < 8; j++) A[j] = 0ull;
            {
                float xs[4] = {xv.x, xv.y, xv.z, xv.w};
                int kb4 = lane * 16;
                #pragma unroll
                for (int kk = 0; kk < 4; kk++) {
                    unsigned long long cp = pack2(xs[kk]);
                    #pragma unroll
                    for (int q = 0; q < 4; q++) {
                        ulonglong2 wv = w1s[kb4 + kk * 4 + q];
                        A[2*q+0] = fma2(cp, wv.x, A[2*q+0]);
                        A[2*q+1] = fma2(cp, wv.y, A[2*q+1]);
                    }
                }
            }
            float a[16];
            #pragma unroll
            for (int p = 0; p < 8; p++) unpack2(A[p], a[2*p], a[2*p+1]);
            {   // halving butterfly
                float t[16];
                #pragma unroll
                for (int i = 0; i < 16; i++) t[i] = __shfl_xor_sync(~0u, a[i], 16);
                if ((lane & 16) == 0) {
                    #pragma unroll
                    for (int i = 0; i < 8; i++) a[i] += t[i]; }
                else {
                    #pragma unroll
                    for (int i = 0; i < 8; i++) a[i] = a[i+8] + t[i+8]; }
            }
            {
                float t[8];
                #pragma unroll
                for (int i = 0; i < 8; i++) t[i] = __shfl_xor_sync(~0u, a[i], 8);
                if ((lane & 8) == 0) {
                    #pragma unroll
                    for (int i = 0; i < 4; i++) a[i] += t[i]; }
                else {
                    #pragma unroll
                    for (int i = 0; i < 4; i++) a[i] = a[i+4] + t[i+4]; }
            }
            {
                float t[4];
                #pragma unroll
                for (int i = 0; i < 4; i++) t[i] = __shfl_xor_sync(~0u, a[i], 4);
                if ((lane & 4) == 0) { a[0] += t[0]; a[1] += t[1]; }
                else                 { a[0] = a[2] + t[2]; a[1] = a[3] + t[3]; }
            }
            {
                float t0 = __shfl_xor_sync(~0u, a[0], 2);
                float t1 = __shfl_xor_sync(~0u, a[1], 2);
                if ((lane & 2) == 0) a[0] += t0; else a[0] = a[1] + t1;
            }
            a[0] += __shfl_xor_sync(~0u, a[0], 1);
            float vres = a[0] * dvd;
            float vhi = __shfl_down_sync(~0u, vres, 2);
            if ((lane & 3) == 0)
                ((__half2*)g_h1h)[(size_t)w * 8 + (lane >> 2)] =
                    __floats2half2_rn(vres, vhi);
            xv = xvN;
        }
    }
    grid_sync(3);

    // ================= P4: prop1 (HADD2 + 2-deep csrc prefetch) ============
    if (bid == GRID - 1 && tid < NUM_G) g_pcnt[tid] = 0;
    {
        const int sub = lane & 3, grp = lane >> 2;
        const __half2 h2z = __floats2half2_rn(0.f, 0.f);
        int w = gw;
        int dgC = 0, stC = 0, dgN = 0, stN = 0, s0C = 0, s1C = 0;
        if (w < NUM_N) {
            dgC = g_deg[w]; stC = g_woff[w];
            if (grp < dgC)     s0C = g_csrc[stC + grp];
            if (grp + 8 < dgC) s1C = g_csrc[stC + grp + 8];
            int wn = w + NWARP;
            if (wn < NUM_N) { dgN = g_deg[wn]; stN = g_woff[wn]; }
        }
        for (; w < NUM_N; w += NWARP) {
            int wn2 = w + 2 * NWARP;
            int dgN2 = 0, stN2 = 0;
            if (wn2 < NUM_N) { dgN2 = g_deg[wn2]; stN2 = g_woff[wn2]; }
            int s0N = 0, s1N = 0;
            if (grp < dgN)     s0N = g_csrc[stN + grp];
            if (grp + 8 < dgN) s1N = g_csrc[stN + grp + 8];
            __half2 p0 = h2z, p1 = h2z, q0 = h2z, q1 = h2z;
            if (grp < dgC)     gatherh2(g_h1h, s0C, sub, p0, p1);
            if (grp + 8 < dgC) gatherh2(g_h1h, s1C, sub, q0, q1);
            for (int e = grp + 16; e < dgC; e += 16) {
                int s0 = g_csrc[stC + e];
                int s1 = (e + 8 < dgC) ? g_csrc[stC + e + 8] : 0;
                gatherh2(g_h1h, s0, sub, p0, p1);
                if (e + 8 < dgC) gatherh2(g_h1h, s1, sub, q0, q1);
            }
            float2 fp0 = __half22float2(p0), fp1 = __half22float2(p1);
            float2 fq0 = __half22float2(q0), fq1 = __half22float2(q1);
            float ax = fp0.x + fq0.x, ay = fp0.y + fq0.y;
            float az = fp1.x + fq1.x, aw = fp1.y + fq1.y;
            #pragma unroll
            for (int o = 4; o < 32; o <<= 1) {
                ax += __shfl_xor_sync(~0u, ax, o);
                ay += __shfl_xor_sync(~0u, ay, o);
                az += __shfl_xor_sync(~0u, az, o);
                aw += __shfl_xor_sync(~0u, aw, o);
            }
            if (lane < 4) {
                float dvd = g_dinv[w];
                float hx, hy, hz, hw;
                read16h(g_h1h, w, sub, hx, hy, hz, hw);
                float4 bv = ((const float4*)b1)[sub];
                float ox = fmaxf(fmaf(dvd, ax + hx, bv.x), 0.f) * dvd;
                float oy = fmaxf(fmaf(dvd, ay + hy, bv.y), 0.f) * dvd;
                float oz = fmaxf(fmaf(dvd, az + hz, bv.z), 0.f) * dvd;
                float ow = fmaxf(fmaf(dvd, aw + hw, bv.w), 0.f) * dvd;
                uint2 u;
                *(__half2*)&u.x = __floats2half2_rn(ox, oy);
                *(__half2*)&u.y = __floats2half2_rn(oz, ow);
                ((uint2*)g_qh)[(size_t)w * 4 + sub] = u;
            }
            dgC = dgN; stC = stN; dgN = dgN2; stN = stN2;
            s0C = s0N; s1C = s1N;
        }
    }
    grid_sync(4);

    // ================= P5: prop2 (HADD2 + 2-deep csrc prefetch) ============
    {
        const int sub = lane & 3, grp = lane >> 2;
        const __half2 h2z = __floats2half2_rn(0.f, 0.f);
        int w = gw;
        int dgC = 0, stC = 0, dgN = 0, stN = 0, s0C = 0, s1C = 0;
        if (w < NUM_N) {
            dgC = g_deg[w]; stC = g_woff[w];
            if (grp < dgC)     s0C = g_csrc[stC + grp];
            if (grp + 8 < dgC) s1C = g_csrc[stC + grp + 8];
            int wn = w + NWARP;
            if (wn < NUM_N) { dgN = g_deg[wn]; stN = g_woff[wn]; }
        }
        for (; w < NUM_N; w += NWARP) {
            int wn2 = w + 2 * NWARP;
            int dgN2 = 0, stN2 = 0;
            if (wn2 < NUM_N) { dgN2 = g_deg[wn2]; stN2 = g_woff[wn2]; }
            int s0N = 0, s1N = 0;
            if (grp < dgN)     s0N = g_csrc[stN + grp];
            if (grp + 8 < dgN) s1N = g_csrc[stN + grp + 8];
            __half2 p0 = h2z, p1 = h2z, q0 = h2z, q1 = h2z;
            if (grp < dgC)     gatherh2(g_qh, s0C, sub, p0, p1);
            if (grp + 8 < dgC) gatherh2(g_qh, s1C, sub, q0, q1);
            for (int e = grp + 16; e < dgC; e += 16) {
                int s0 = g_csrc[stC + e];
                int s1 = (e + 8 < dgC) ? g_csrc[stC + e + 8] : 0;
                gatherh2(g_qh, s0, sub, p0, p1);
                if (e + 8 < dgC) gatherh2(g_qh, s1, sub, q0, q1);
            }
            float2 fp0 = __half22float2(p0), fp1 = __half22float2(p1);
            float2 fq0 = __half22float2(q0), fq1 = __half22float2(q1);
            float ax = fp0.x + fq0.x, ay = fp0.y + fq0.y;
            float az = fp1.x + fq1.x, aw = fp1.y + fq1.y;
            #pragma unroll
            for (int o = 4; o < 32; o <<= 1) {
                ax += __shfl_xor_sync(~0u, ax, o);
                ay += __shfl_xor_sync(~0u, ay, o);
                az += __shfl_xor_sync(~0u, az, o);
                aw += __shfl_xor_sync(~0u, aw, o);
            }
            if (lane < 4) {
                float dvd = g_dinv[w];
                float qx, qy, qz, qw;
                read16h(g_qh, w, sub, qx, qy, qz, qw);
                float4 o;
                o.x = dvd * (ax + qx); o.y = dvd * (ay + qy);
                o.z = dvd * (az + qz); o.w = dvd * (aw + qw);
                ((float4*)g_r)[(size_t)w * 4 + sub] = o;
            }
            dgC = dgN; stC = stN; dgN = dgN2; stN = stN2;
            s0C = s0N; s1C = s1N;
        }
    }
    grid_sync(5);

    // ================= P6: pool + gemm2 + mlp (blocks 0..127) ==============
    if (bid < NUM_G) {
        for (int i = tid; i < 512; i += TPB) w2s[i] = ((const float4*)W2)[i];
        __syncthreads();
        const int g = bid;
        const int cnt = g_pcnt2[g];
        const int start = g_boff[g];
        float4 bv = ((const float4*)b2)[lane];
        float4 sum = make_float4(0.f, 0.f, 0.f, 0.f);
        int i = wid;
        float rvN = 0.f;
        if (i < cnt) {
            int n = g_bnode[start + i];
            rvN = (lane < 16) ? g_r[n * 16 + lane] : 0.f;
        }
        for (; i < cnt; i += 32) {
            float rv = rvN;
            int in2 = i + 32;
            if (in2 < cnt) {
                int n2 = g_bnode[start + in2];
                rvN = (lane < 16) ? g_r[n2 * 16 + lane] : 0.f;
            }
            float4 acc = bv;
            #pragma unroll
            for (int k = 0; k < 16; k++) {
                float s = __shfl_sync(~0u, rv, k);
                float4 wv = w2s[k * 32 + lane];
                acc.x = fmaf(s, wv.x, acc.x); acc.y = fmaf(s, wv.y, acc.y);
                acc.z = fmaf(s, wv.z, acc.z); acc.w = fmaf(s, wv.w, acc.w);
            }
            sum.x += fmaxf(acc.x, 0.f); sum.y += fmaxf(acc.y, 0.f);
            sum.z += fmaxf(acc.z, 0.f); sum.w += fmaxf(acc.w, 0.f);
        }
        red[wid * 32 + lane] = sum;
        __syncthreads();
        if (tid < 32) {
            float4 tot = red[tid];
            #pragma unroll
            for (int w2 = 1; w2 < 32; w2++) {
                float4 vv = red[w2 * 32 + tid];
                tot.x += vv.x; tot.y += vv.y; tot.z += vv.z; tot.w += vv.w;
            }
            float inv = 1.f / fmaxf((float)cnt, 1.f);
            ps[tid * 4 + 0] = tot.x * inv; ps[tid * 4 + 1] = tot.y * inv;
            ps[tid * 4 + 2] = tot.z * inv; ps[tid * 4 + 3] = tot.w * inv;
        }
        __syncthreads();
        if (tid < 128) {
            float acc = Lb1[tid];
            #pragma unroll 8
            for (int k = 0; k < 128; k++) acc = fmaf(ps[k], LW1[k * 128 + tid], acc);
            z1[tid] = fmaxf(acc, 0.f);
        }
        __syncthreads();
        if (tid < 2) {
            float a = Lb2[tid];
            for (int k = 0; k < 128; k++) a = fmaf(z1[k], LW2[k * 2 + tid], a);
            z2[tid] = a;
        }
        __syncthreads();
        if (tid == 0) {
            float m = fmaxf(z2[0], z2[1]);
            float lse = m + logf(expf(z2[0] - m) + expf(z2[1] - m));
            out[g * 2 + 0] = z2[0] - lse;
            out[g * 2 + 1] = z2[1] - lse;
        }
    } else {
        for (int i = (bid - NUM_G) * TPB + tid; i < NUM_N; i += (GRID - NUM_G) * TPB)
            g_deg[i] = 0;
    }
}

// -------- launch --------
extern "C" void kernel_launch(void* const* d_in, const int* in_sizes, int n_in,
                              void* d_out, int out_size) {
    const float* x   = (const float*)d_in[0];
    const void*  ei  = d_in[1];
    const void*  bat = d_in[2];
    const float* W1  = (const float*)d_in[3];
    const float* b1  = (const float*)d_in[4];
    const float* W2  = (const float*)d_in[5];
    const float* b2  = (const float*)d_in[6];
    const float* LW1 = (const float*)d_in[7];
    const float* Lb1 = (const float*)d_in[8];
    const float* LW2 = (const float*)d_in[9];
    const float* Lb2 = (const float*)d_in[10];
    float* out = (float*)d_out;

    mega_kernel<<<GRID, TPB>>>(x, ei, bat, W1, b1, W2, b2,
                               LW1, Lb1, LW2, Lb2, out);
}

// round 12
// speedup vs baseline: 1.4226x; 1.0385x over previous
#include <cuda_runtime.h>
#include <cuda_fp16.h>
#include <math.h>

#define NUM_N 100000
#define NUM_E 1600000
#define NUM_G 128
#define D_IN 128

#define GRID  148
#define TPB   1024
#define GT    (GRID * TPB)        // 151552 threads
#define NWARP (GT / 32)           // 4736 warps
#define CHUNK 676                 // 148*676 >= NUM_N
#define NE2   (NUM_E / 2)         // 800000 edge pairs

// -------- device scratch (statics start zeroed) ----------------------------
__device__ int    g_bar[8];
__device__ int    g_batch[NUM_N];
__device__ int    g_deg[NUM_N];      // re-zeroed for replay in P6
__device__ float  g_dinv[NUM_N];
__device__ int    g_woff[NUM_N];     // pristine CSR start offsets
__device__ int    g_erank[NUM_E];    // per-edge rank within dst bucket
__device__ int    g_nrank[NUM_N];    // per-node rank within graph bucket
__device__ int    g_csrc[NUM_E];
__device__ int    g_bsum[GRID];
__device__ int    g_pcnt[NUM_G];     // re-zeroed in P4
__device__ int    g_pcnt2[NUM_G];    // pristine copy for pool
__device__ int    g_boff[NUM_G];     // pristine batch CSR offsets
__device__ int    g_bnode[NUM_N];
__device__ __half g_h1h[NUM_N * 16];
__device__ __half g_qh [NUM_N * 16];
__device__ float  g_r  [NUM_N * 16];

// -------- software grid barrier -------------------------------------------
__device__ __forceinline__ void grid_sync(int j) {
    __syncthreads();
    __threadfence();
    if (threadIdx.x == 0) {
        if (atomicAdd(&g_bar[j], 1) == GRID - 1) {
            atomicExch(&g_bar[(j + 4) % 6], 0);
        } else {
            while (*((volatile int*)&g_bar[j]) < GRID) { }
        }
    }
    __syncthreads();
    __threadfence();
}

// fp16 gather + HADD2 accumulate
__device__ __forceinline__ void gatherh2(const __half* base, int s, int sub,
                                         __half2& a0, __half2& a1) {
    uint2 u = ((const uint2*)(base))[s * 4 + sub];
    a0 = __hadd2(a0, *(__half2*)&u.x);
    a1 = __hadd2(a1, *(__half2*)&u.y);
}

// fp32 read of one node's 4-half chunk
__device__ __forceinline__ void read16h(const __half* base, int s, int sub,
                                        float& x0, float& y0, float& z0, float& w0) {
    uint2 u = ((const uint2*)(base))[s * 4 + sub];
    float2 f0 = __half22float2(*(__half2*)&u.x);
    float2 f1 = __half22float2(*(__half2*)&u.y);
    x0 = f0.x; y0 = f0.y; z0 = f1.x; w0 = f1.y;
}

// packed f32x2 helpers
__device__ __forceinline__ unsigned long long fma2(unsigned long long c,
                                                   unsigned long long w,
                                                   unsigned long long a) {
    unsigned long long d;
    asm("fma.rn.f32x2 %0, %1, %2, %3;" : "=l"(d) : "l"(c), "l"(w), "l"(a));
    return d;
}
__device__ __forceinline__ unsigned long long pack2(float c) {
    unsigned long long d;
    asm("mov.b64 %0, {%1, %1};" : "=l"(d) : "f"(c));
    return d;
}
__device__ __forceinline__ void unpack2(unsigned long long p, float& lo, float& hi) {
    asm("mov.b64 {%0, %1}, %2;" : "=f"(lo), "=f"(hi) : "l"(p));
}

__global__ __launch_bounds__(TPB, 1) void mega_kernel(
    const float* __restrict__ x, const void* ei, const void* bat,
    const float* __restrict__ W1, const float* __restrict__ b1,
    const float* __restrict__ W2, const float* __restrict__ b2,
    const float* __restrict__ LW1, const float* __restrict__ Lb1,
    const float* __restrict__ LW2, const float* __restrict__ Lb2,
    float* __restrict__ out)
{
    __shared__ ulonglong2 w1s[512];   // W1 as f32x2 pairs
    __shared__ float4 w2s[512];
    __shared__ float4 red[1024];
    __shared__ int    wsum[32];
    __shared__ int    s_i32, s_base;
    __shared__ float  ps[128], z1[128], z2[2];

    const int tid  = threadIdx.x, bid = blockIdx.x;
    const int lane = tid & 31,    wid = tid >> 5;
    const int gth  = bid * TPB + tid;
    const int gw   = gth >> 5;

    // ---- detect int64 vs int32 index layout ----
    if (tid == 0) s_i32 = 0;
    __syncthreads();
    if (tid < 64) {
        long long v = ((const long long*)ei)[(size_t)tid * (NUM_E / 64)];
        if (v < 0 || v >= (long long)NUM_N) s_i32 = 1;
    }
    __syncthreads();
    const bool f64 = (s_i32 == 0);

    // ================= P0: histograms + rank capture =======================
    for (int i = gth; i < NE2; i += GT) {
        int d0, d1;
        if (f64) { int4 v = ((const int4*)ei)[NE2 + i]; d0 = v.x; d1 = v.z; }
        else     { int2 v = ((const int2*)ei)[NE2 + i]; d0 = v.x; d1 = v.y; }
        int r0 = atomicAdd(&g_deg[d0], 1);
        int r1 = atomicAdd(&g_deg[d1], 1);
        ((int2*)g_erank)[i] = make_int2(r0, r1);
    }
    for (int i = gth; i < NUM_N; i += GT) {
        int b = f64 ? (int)((const long long*)bat)[i] : ((const int*)bat)[i];
        g_batch[i] = b;
        g_nrank[i] = atomicAdd(&g_pcnt[b], 1);
    }
    grid_sync(0);

    // ================= P1: block-local scan of deg (+dinv, batch scan) =====
    const int node = bid * CHUNK + tid;
    const bool nvalid = (tid < CHUNK) && (node < NUM_N);
    int deg = nvalid ? g_deg[node] : 0;
    int v = deg;
    #pragma unroll
    for (int o = 1; o < 32; o <<= 1) {
        int n = __shfl_up_sync(~0u, v, o);
        if (lane >= o) v += n;
    }
    if (lane == 31) wsum[wid] = v;
    __syncthreads();
    if (wid == 0) {
        int wv = wsum[lane];
        #pragma unroll
        for (int o = 1; o < 32; o <<= 1) {
            int n = __shfl_up_sync(~0u, wv, o);
            if (lane >= o) wv += n;
        }
        wsum[lane] = wv;
    }
    __syncthreads();
    const int ex_local = (wid ? wsum[wid - 1] : 0) + v - deg;
    if (tid == 0) g_bsum[bid] = wsum[31];
    if (nvalid) g_dinv[node] = rsqrtf((float)deg + 1.f);
    if (bid == 0 && wid == 31) {
        int p0 = g_pcnt[lane*4+0], p1 = g_pcnt[lane*4+1];
        int p2 = g_pcnt[lane*4+2], p3 = g_pcnt[lane*4+3];
        int t1 = p0 + p1, t2 = t1 + p2, t3 = t2 + p3;
        int vv = t3;
        #pragma unroll
        for (int o = 1; o < 32; o <<= 1) {
            int n = __shfl_up_sync(~0u, vv, o);
            if (lane >= o) vv += n;
        }
        int exb = vv - t3;
        g_boff[lane*4+0] = exb;
        g_boff[lane*4+1] = exb + p0;
        g_boff[lane*4+2] = exb + t1;
        g_boff[lane*4+3] = exb + t2;
        g_pcnt2[lane*4+0] = p0; g_pcnt2[lane*4+1] = p1;
        g_pcnt2[lane*4+2] = p2; g_pcnt2[lane*4+3] = p3;
    }
    grid_sync(1);

    // ================= P2: per-block global base, write woff ===============
    if (wid == 0) {
        int s = 0;
        for (int i = lane; i < bid; i += 32) s += g_bsum[i];
        #pragma unroll
        for (int o = 16; o; o >>= 1) s += __shfl_xor_sync(~0u, s, o);
        if (lane == 0) s_base = s;
    }
    __syncthreads();
    if (nvalid) g_woff[node] = s_base + ex_local;
    grid_sync(2);

    // ================= P3: atomic-free scatter (x2 unroll) + bnode + gemm1 =
    for (int i = gth; i < NE2; i += 2 * GT) {
        int s0, s1, d0, d1;
        if (f64) {
            int4 sv = ((const int4*)ei)[i];       s0 = sv.x; s1 = sv.z;
            int4 dv = ((const int4*)ei)[NE2 + i]; d0 = dv.x; d1 = dv.z;
        } else {
            int2 sv = ((const int2*)ei)[i];       s0 = sv.x; s1 = sv.y;
            int2 dv = ((const int2*)ei)[NE2 + i]; d0 = dv.x; d1 = dv.y;
        }
        int2 rkA = ((const int2*)g_erank)[i];
        int i2 = i + GT;
        bool have2 = (i2 < NE2);
        int s2 = 0, s3 = 0, d2 = 0, d3 = 0;
        int2 rkB = make_int2(0, 0);
        if (have2) {
            if (f64) {
                int4 sv = ((const int4*)ei)[i2];       s2 = sv.x; s3 = sv.z;
                int4 dv = ((const int4*)ei)[NE2 + i2]; d2 = dv.x; d3 = dv.z;
            } else {
                int2 sv = ((const int2*)ei)[i2];       s2 = sv.x; s3 = sv.y;
                int2 dv = ((const int2*)ei)[NE2 + i2]; d2 = dv.x; d3 = dv.y;
            }
            rkB = ((const int2*)g_erank)[i2];
        }
        int w0 = g_woff[d0];
        int w1 = g_woff[d1];
        int w2 = have2 ? g_woff[d2] : 0;
        int w3 = have2 ? g_woff[d3] : 0;
        g_csrc[w0 + rkA.x] = s0;
        g_csrc[w1 + rkA.y] = s1;
        if (have2) {
            g_csrc[w2 + rkB.x] = s2;
            g_csrc[w3 + rkB.y] = s3;
        }
    }
    for (int i = gth; i < NUM_N; i += GT) {
        g_bnode[g_boff[g_batch[i]] + g_nrank[i]] = i;
    }
    for (int i = tid; i < 512; i += TPB) w1s[i] = ((const ulonglong2*)W1)[i];
    __syncthreads();
    {   // gemm1: f32x2 packed FMAs, double-buffered x row, fp16 output
        int w = gw;
        float4 xv = make_float4(0.f, 0.f, 0.f, 0.f);
        if (w < NUM_N) xv = ((const float4*)x)[(size_t)w * 32 + lane];
        for (; w < NUM_N; w += NWARP) {
            int wn = w + NWARP;
            float4 xvN = make_float4(0.f, 0.f, 0.f, 0.f);
            if (wn < NUM_N) xvN = ((const float4*)x)[(size_t)wn * 32 + lane];
            float dvd = g_dinv[w];
            unsigned long long A[8];
            #pragma unroll
            for (int j = 0; j < 8; j++) A[j] = 0ull;
            {
                float xs[4] = {xv.x, xv.y, xv.z, xv.w};
                int kb4 = lane * 16;
                #pragma unroll
                for (int kk = 0; kk < 4; kk++) {
                    unsigned long long cp = pack2(xs[kk]);
                    #pragma unroll
                    for (int q = 0; q < 4; q++) {
                        ulonglong2 wv = w1s[kb4 + kk * 4 + q];
                        A[2*q+0] = fma2(cp, wv.x, A[2*q+0]);
                        A[2*q+1] = fma2(cp, wv.y, A[2*q+1]);
                    }
                }
            }
            float a[16];
            #pragma unroll
            for (int p = 0; p < 8; p++) unpack2(A[p], a[2*p], a[2*p+1]);
            {   // halving butterfly
                float t[16];
                #pragma unroll
                for (int i = 0; i < 16; i++) t[i] = __shfl_xor_sync(~0u, a[i], 16);
                if ((lane & 16) == 0) {
                    #pragma unroll
                    for (int i = 0; i < 8; i++) a[i] += t[i]; }
                else {
                    #pragma unroll
                    for (int i = 0; i < 8; i++) a[i] = a[i+8] + t[i+8]; }
            }
            {
                float t[8];
                #pragma unroll
                for (int i = 0; i < 8; i++) t[i] = __shfl_xor_sync(~0u, a[i], 8);
                if ((lane & 8) == 0) {
                    #pragma unroll
                    for (int i = 0; i < 4; i++) a[i] += t[i]; }
                else {
                    #pragma unroll
                    for (int i = 0; i < 4; i++) a[i] = a[i+4] + t[i+4]; }
            }
            {
                float t[4];
                #pragma unroll
                for (int i = 0; i < 4; i++) t[i] = __shfl_xor_sync(~0u, a[i], 4);
                if ((lane & 4) == 0) { a[0] += t[0]; a[1] += t[1]; }
                else                 { a[0] = a[2] + t[2]; a[1] = a[3] + t[3]; }
            }
            {
                float t0 = __shfl_xor_sync(~0u, a[0], 2);
                float t1 = __shfl_xor_sync(~0u, a[1], 2);
                if ((lane & 2) == 0) a[0] += t0; else a[0] = a[1] + t1;
            }
            a[0] += __shfl_xor_sync(~0u, a[0], 1);
            float vres = a[0] * dvd;
            float vhi = __shfl_down_sync(~0u, vres, 2);
            if ((lane & 3) == 0)
                ((__half2*)g_h1h)[(size_t)w * 8 + (lane >> 2)] =
                    __floats2half2_rn(vres, vhi);
            xv = xvN;
        }
    }
    grid_sync(3);

    // ================= P4: prop1 — TWO nodes per warp (16 lanes each) ======
    if (bid == GRID - 1 && tid < NUM_G) g_pcnt[tid] = 0;
    {
        const int sub  = lane & 3;
        const int grp  = (lane >> 2) & 3;    // edge slot 0..3 within half
        const int nsel = lane >> 4;          // node select 0/1
        const int stride = 2 * NWARP;
        const __half2 h2z = __floats2half2_rn(0.f, 0.f);
        int w = gw * 2;                      // pair base (always < NUM_N)
        int dgC = 0, stC = 0, dgN = 0, stN = 0, s0C = 0, s1C = 0;
        {
            int myn = w + nsel;
            dgC = g_deg[myn]; stC = g_woff[myn];
            if (grp < dgC)     s0C = g_csrc[stC + grp];
            if (grp + 4 < dgC) s1C = g_csrc[stC + grp + 4];
            int wn = myn + stride;
            if (wn < NUM_N) { dgN = g_deg[wn]; stN = g_woff[wn]; }
        }
        for (; w < NUM_N; w += stride) {
            int curn = w + nsel;
            int wn2 = curn + 2 * stride;
            int dgN2 = 0, stN2 = 0;
            if (wn2 < NUM_N) { dgN2 = g_deg[wn2]; stN2 = g_woff[wn2]; }
            int s0N = 0, s1N = 0;
            if (grp < dgN)     s0N = g_csrc[stN + grp];
            if (grp + 4 < dgN) s1N = g_csrc[stN + grp + 4];
            __half2 p0 = h2z, p1 = h2z, q0 = h2z, q1 = h2z;
            if (grp < dgC)     gatherh2(g_h1h, s0C, sub, p0, p1);
            if (grp + 4 < dgC) gatherh2(g_h1h, s1C, sub, q0, q1);
            for (int e = grp + 8; e < dgC; e += 8) {
                int s0 = g_csrc[stC + e];
                int s1 = (e + 4 < dgC) ? g_csrc[stC + e + 4] : 0;
                gatherh2(g_h1h, s0, sub, p0, p1);
                if (e + 4 < dgC) gatherh2(g_h1h, s1, sub, q0, q1);
            }
            float2 fp0 = __half22float2(p0), fp1 = __half22float2(p1);
            float2 fq0 = __half22float2(q0), fq1 = __half22float2(q1);
            float ax = fp0.x + fq0.x, ay = fp0.y + fq0.y;
            float az = fp1.x + fq1.x, aw = fp1.y + fq1.y;
            #pragma unroll
            for (int o = 4; o < 16; o <<= 1) {     // offsets 4, 8 (stay in half)
                ax += __shfl_xor_sync(~0u, ax, o);
                ay += __shfl_xor_sync(~0u, ay, o);
                az += __shfl_xor_sync(~0u, az, o);
                aw += __shfl_xor_sync(~0u, aw, o);
            }
            if ((lane & 12) == 0) {                // lanes 0-3 and 16-19
                float dvd = g_dinv[curn];
                float hx, hy, hz, hw;
                read16h(g_h1h, curn, sub, hx, hy, hz, hw);
                float4 bv = ((const float4*)b1)[sub];
                float ox = fmaxf(fmaf(dvd, ax + hx, bv.x), 0.f) * dvd;
                float oy = fmaxf(fmaf(dvd, ay + hy, bv.y), 0.f) * dvd;
                float oz = fmaxf(fmaf(dvd, az + hz, bv.z), 0.f) * dvd;
                float ow = fmaxf(fmaf(dvd, aw + hw, bv.w), 0.f) * dvd;
                uint2 u;
                *(__half2*)&u.x = __floats2half2_rn(ox, oy);
                *(__half2*)&u.y = __floats2half2_rn(oz, ow);
                ((uint2*)g_qh)[(size_t)curn * 4 + sub] = u;
            }
            dgC = dgN; stC = stN; dgN = dgN2; stN = stN2;
            s0C = s0N; s1C = s1N;
        }
    }
    grid_sync(4);

    // ================= P5: prop2 — TWO nodes per warp ======================
    {
        const int sub  = lane & 3;
        const int grp  = (lane >> 2) & 3;
        const int nsel = lane >> 4;
        const int stride = 2 * NWARP;
        const __half2 h2z = __floats2half2_rn(0.f, 0.f);
        int w = gw * 2;
        int dgC = 0, stC = 0, dgN = 0, stN = 0, s0C = 0, s1C = 0;
        {
            int myn = w + nsel;
            dgC = g_deg[myn]; stC = g_woff[myn];
            if (grp < dgC)     s0C = g_csrc[stC + grp];
            if (grp + 4 < dgC) s1C = g_csrc[stC + grp + 4];
            int wn = myn + stride;
            if (wn < NUM_N) { dgN = g_deg[wn]; stN = g_woff[wn]; }
        }
        for (; w < NUM_N; w += stride) {
            int curn = w + nsel;
            int wn2 = curn + 2 * stride;
            int dgN2 = 0, stN2 = 0;
            if (wn2 < NUM_N) { dgN2 = g_deg[wn2]; stN2 = g_woff[wn2]; }
            int s0N = 0, s1N = 0;
            if (grp < dgN)     s0N = g_csrc[stN + grp];
            if (grp + 4 < dgN) s1N = g_csrc[stN + grp + 4];
            __half2 p0 = h2z, p1 = h2z, q0 = h2z, q1 = h2z;
            if (grp < dgC)     gatherh2(g_qh, s0C, sub, p0, p1);
            if (grp + 4 < dgC) gatherh2(g_qh, s1C, sub, q0, q1);
            for (int e = grp + 8; e < dgC; e += 8) {
                int s0 = g_csrc[stC + e];
                int s1 = (e + 4 < dgC) ? g_csrc[stC + e + 4] : 0;
                gatherh2(g_qh, s0, sub, p0, p1);
                if (e + 4 < dgC) gatherh2(g_qh, s1, sub, q0, q1);
            }
            float2 fp0 = __half22float2(p0), fp1 = __half22float2(p1);
            float2 fq0 = __half22float2(q0), fq1 = __half22float2(q1);
            float ax = fp0.x + fq0.x, ay = fp0.y + fq0.y;
            float az = fp1.x + fq1.x, aw = fp1.y + fq1.y;
            #pragma unroll
            for (int o = 4; o < 16; o <<= 1) {
                ax += __shfl_xor_sync(~0u, ax, o);
                ay += __shfl_xor_sync(~0u, ay, o);
                az += __shfl_xor_sync(~0u, az, o);
                aw += __shfl_xor_sync(~0u, aw, o);
            }
            if ((lane & 12) == 0) {
                float dvd = g_dinv[curn];
                float qx, qy, qz, qw;
                read16h(g_qh, curn, sub, qx, qy, qz, qw);
                float4 o;
                o.x = dvd * (ax + qx); o.y = dvd * (ay + qy);
                o.z = dvd * (az + qz); o.w = dvd * (aw + qw);
                ((float4*)g_r)[(size_t)curn * 4 + sub] = o;
            }
            dgC = dgN; stC = stN; dgN = dgN2; stN = stN2;
            s0C = s0N; s1C = s1N;
        }
    }
    grid_sync(5);

    // ================= P6: pool + gemm2 + mlp (blocks 0..127) ==============
    if (bid < NUM_G) {
        for (int i = tid; i < 512; i += TPB) w2s[i] = ((const float4*)W2)[i];
        __syncthreads();
        const int g = bid;
        const int cnt = g_pcnt2[g];
        const int start = g_boff[g];
        float4 bv = ((const float4*)b2)[lane];
        float4 sum = make_float4(0.f, 0.f, 0.f, 0.f);
        int i = wid;
        float rvN = 0.f;
        if (i < cnt) {
            int n = g_bnode[start + i];
            rvN = (lane < 16) ? g_r[n * 16 + lane] : 0.f;
        }
        for (; i < cnt; i += 32) {
            float rv = rvN;
            int in2 = i + 32;
            if (in2 < cnt) {
                int n2 = g_bnode[start + in2];
                rvN = (lane < 16) ? g_r[n2 * 16 + lane] : 0.f;
            }
            float4 acc = bv;
            #pragma unroll
            for (int k = 0; k < 16; k++) {
                float s = __shfl_sync(~0u, rv, k);
                float4 wv = w2s[k * 32 + lane];
                acc.x = fmaf(s, wv.x, acc.x); acc.y = fmaf(s, wv.y, acc.y);
                acc.z = fmaf(s, wv.z, acc.z); acc.w = fmaf(s, wv.w, acc.w);
            }
            sum.x += fmaxf(acc.x, 0.f); sum.y += fmaxf(acc.y, 0.f);
            sum.z += fmaxf(acc.z, 0.f); sum.w += fmaxf(acc.w, 0.f);
        }
        red[wid * 32 + lane] = sum;
        __syncthreads();
        if (tid < 32) {
            float4 tot = red[tid];
            #pragma unroll
            for (int w2 = 1; w2 < 32; w2++) {
                float4 vv = red[w2 * 32 + tid];
                tot.x += vv.x; tot.y += vv.y; tot.z += vv.z; tot.w += vv.w;
            }
            float inv = 1.f / fmaxf((float)cnt, 1.f);
            ps[tid * 4 + 0] = tot.x * inv; ps[tid * 4 + 1] = tot.y * inv;
            ps[tid * 4 + 2] = tot.z * inv; ps[tid * 4 + 3] = tot.w * inv;
        }
        __syncthreads();
        if (tid < 128) {
            float acc = Lb1[tid];
            #pragma unroll 8
            for (int k = 0; k < 128; k++) acc = fmaf(ps[k], LW1[k * 128 + tid], acc);
            z1[tid] = fmaxf(acc, 0.f);
        }
        __syncthreads();
        if (tid < 2) {
            float a = Lb2[tid];
            for (int k = 0; k < 128; k++) a = fmaf(z1[k], LW2[k * 2 + tid], a);
            z2[tid] = a;
        }
        __syncthreads();
        if (tid == 0) {
            float m = fmaxf(z2[0], z2[1]);
            float lse = m + logf(expf(z2[0] - m) + expf(z2[1] - m));
            out[g * 2 + 0] = z2[0] - lse;
            out[g * 2 + 1] = z2[1] - lse;
        }
    } else {
        for (int i = (bid - NUM_G) * TPB + tid; i < NUM_N; i += (GRID - NUM_G) * TPB)
            g_deg[i] = 0;
    }
}

// -------- launch --------
extern "C" void kernel_launch(void* const* d_in, const int* in_sizes, int n_in,
                              void* d_out, int out_size) {
    const float* x   = (const float*)d_in[0];
    const void*  ei  = d_in[1];
    const void*  bat = d_in[2];
    const float* W1  = (const float*)d_in[3];
    const float* b1  = (const float*)d_in[4];
    const float* W2  = (const float*)d_in[5];
    const float* b2  = (const float*)d_in[6];
    const float* LW1 = (const float*)d_in[7];
    const float* Lb1 = (const float*)d_in[8];
    const float* LW2 = (const float*)d_in[9];
    const float* Lb2 = (const float*)d_in[10];
    float* out = (float*)d_out;

    mega_kernel<<<GRID, TPB>>>(x, ei, bat, W1, b1, W2, b2,
                               LW1, Lb1, LW2, Lb2, out);
}

// round 14
// speedup vs baseline: 1.4564x; 1.0238x over previous
#include <cuda_runtime.h>
#include <cuda_fp16.h>
#include <math.h>

#define NUM_N 100000
#define NUM_E 1600000
#define NUM_G 128
#define D_IN 128

#define GRID  148
#define TPB   1024
#define GT    (GRID * TPB)        // 151552 threads
#define NWARP (GT / 32)           // 4736 warps
#define CHUNK 676                 // 148*676 >= NUM_N
#define NE2   (NUM_E / 2)         // 800000 edge pairs

// -------- device scratch (statics start zeroed) ----------------------------
__device__ int    g_bar[8];
__device__ int    g_batch[NUM_N];
__device__ int    g_deg[NUM_N];      // re-zeroed for replay in P6
__device__ float  g_dinv[NUM_N];
__device__ int    g_woff[NUM_N];     // pristine CSR start offsets
__device__ int    g_erank[NUM_E];    // per-edge rank within dst bucket
__device__ int    g_nrank[NUM_N];    // per-node rank within graph bucket
__device__ int    g_csrc[NUM_E];
__device__ int    g_bsum[GRID];
__device__ int    g_pcnt[NUM_G];     // re-zeroed in P4
__device__ int    g_pcnt2[NUM_G];    // pristine copy for pool
__device__ int    g_boff[NUM_G];     // pristine batch CSR offsets
__device__ int    g_bnode[NUM_N];
__device__ __half g_h1h[NUM_N * 16];
__device__ __half g_qh [NUM_N * 16];
__device__ float  g_r  [NUM_N * 16];

// -------- software grid barrier -------------------------------------------
__device__ __forceinline__ void grid_sync(int j) {
    __syncthreads();
    __threadfence();
    if (threadIdx.x == 0) {
        if (atomicAdd(&g_bar[j], 1) == GRID - 1) {
            atomicExch(&g_bar[(j + 4) % 6], 0);
        } else {
            while (*((volatile int*)&g_bar[j]) < GRID) { }
        }
    }
    __syncthreads();
    __threadfence();
}

// fp16 gather + HADD2 accumulate
__device__ __forceinline__ void gatherh2(const __half* base, int s, int sub,
                                         __half2& a0, __half2& a1) {
    uint2 u = ((const uint2*)(base))[s * 4 + sub];
    a0 = __hadd2(a0, *(__half2*)&u.x);
    a1 = __hadd2(a1, *(__half2*)&u.y);
}

// fp32 read of one node's 4-half chunk
__device__ __forceinline__ void read16h(const __half* base, int s, int sub,
                                        float& x0, float& y0, float& z0, float& w0) {
    uint2 u = ((const uint2*)(base))[s * 4 + sub];
    float2 f0 = __half22float2(*(__half2*)&u.x);
    float2 f1 = __half22float2(*(__half2*)&u.y);
    x0 = f0.x; y0 = f0.y; z0 = f1.x; w0 = f1.y;
}

// packed f32x2 helpers
__device__ __forceinline__ unsigned long long fma2(unsigned long long c,
                                                   unsigned long long w,
                                                   unsigned long long a) {
    unsigned long long d;
    asm("fma.rn.f32x2 %0, %1, %2, %3;" : "=l"(d) : "l"(c), "l"(w), "l"(a));
    return d;
}
__device__ __forceinline__ unsigned long long pack2(float c) {
    unsigned long long d;
    asm("mov.b64 %0, {%1, %1};" : "=l"(d) : "f"(c));
    return d;
}
__device__ __forceinline__ void unpack2(unsigned long long p, float& lo, float& hi) {
    asm("mov.b64 {%0, %1}, %2;" : "=f"(lo), "=f"(hi) : "l"(p));
}

__global__ __launch_bounds__(TPB, 1) void mega_kernel(
    const float* __restrict__ x, const void* ei, const void* bat,
    const float* __restrict__ W1, const float* __restrict__ b1,
    const float* __restrict__ W2, const float* __restrict__ b2,
    const float* __restrict__ LW1, const float* __restrict__ Lb1,
    const float* __restrict__ LW2, const float* __restrict__ Lb2,
    float* __restrict__ out)
{
    __shared__ ulonglong2 w1s[512];   // W1 as f32x2 pairs
    __shared__ float4 w2s[512];
    __shared__ float4 red[1024];
    __shared__ int    wsum[32];
    __shared__ int    s_i32, s_base;
    __shared__ float  ps[128], z1[128], z2[2];

    const int tid  = threadIdx.x, bid = blockIdx.x;
    const int lane = tid & 31,    wid = tid >> 5;
    const int gth  = bid * TPB + tid;
    const int gw   = gth >> 5;

    // ---- detect int64 vs int32 index layout ----
    if (tid == 0) s_i32 = 0;
    __syncthreads();
    if (tid < 64) {
        long long v = ((const long long*)ei)[(size_t)tid * (NUM_E / 64)];
        if (v < 0 || v >= (long long)NUM_N) s_i32 = 1;
    }
    __syncthreads();
    const bool f64 = (s_i32 == 0);

    // ================= P0: histograms + rank capture =======================
    for (int i = gth; i < NE2; i += GT) {
        int d0, d1;
        if (f64) { int4 v = ((const int4*)ei)[NE2 + i]; d0 = v.x; d1 = v.z; }
        else     { int2 v = ((const int2*)ei)[NE2 + i]; d0 = v.x; d1 = v.y; }
        int r0 = atomicAdd(&g_deg[d0], 1);
        int r1 = atomicAdd(&g_deg[d1], 1);
        ((int2*)g_erank)[i] = make_int2(r0, r1);
    }
    for (int i = gth; i < NUM_N; i += GT) {
        int b = f64 ? (int)((const long long*)bat)[i] : ((const int*)bat)[i];
        g_batch[i] = b;
        g_nrank[i] = atomicAdd(&g_pcnt[b], 1);
    }
    grid_sync(0);

    // ================= P1: block-local scan of deg (+dinv, batch scan) =====
    const int node = bid * CHUNK + tid;
    const bool nvalid = (tid < CHUNK) && (node < NUM_N);
    int deg = nvalid ? g_deg[node] : 0;
    int v = deg;
    #pragma unroll
    for (int o = 1; o < 32; o <<= 1) {
        int n = __shfl_up_sync(~0u, v, o);
        if (lane >= o) v += n;
    }
    if (lane == 31) wsum[wid] = v;
    __syncthreads();
    if (wid == 0) {
        int wv = wsum[lane];
        #pragma unroll
        for (int o = 1; o < 32; o <<= 1) {
            int n = __shfl_up_sync(~0u, wv, o);
            if (lane >= o) wv += n;
        }
        wsum[lane] = wv;
    }
    __syncthreads();
    const int ex_local = (wid ? wsum[wid - 1] : 0) + v - deg;
    if (tid == 0) g_bsum[bid] = wsum[31];
    if (nvalid) g_dinv[node] = rsqrtf((float)deg + 1.f);
    if (bid == 0 && wid == 31) {
        int p0 = g_pcnt[lane*4+0], p1 = g_pcnt[lane*4+1];
        int p2 = g_pcnt[lane*4+2], p3 = g_pcnt[lane*4+3];
        int t1 = p0 + p1, t2 = t1 + p2, t3 = t2 + p3;
        int vv = t3;
        #pragma unroll
        for (int o = 1; o < 32; o <<= 1) {
            int n = __shfl_up_sync(~0u, vv, o);
            if (lane >= o) vv += n;
        }
        int exb = vv - t3;
        g_boff[lane*4+0] = exb;
        g_boff[lane*4+1] = exb + p0;
        g_boff[lane*4+2] = exb + t1;
        g_boff[lane*4+3] = exb + t2;
        g_pcnt2[lane*4+0] = p0; g_pcnt2[lane*4+1] = p1;
        g_pcnt2[lane*4+2] = p2; g_pcnt2[lane*4+3] = p3;
    }
    grid_sync(1);

    // ================= P2: per-block global base, write woff ===============
    if (wid == 0) {
        int s = 0;
        for (int i = lane; i < bid; i += 32) s += g_bsum[i];
        #pragma unroll
        for (int o = 16; o; o >>= 1) s += __shfl_xor_sync(~0u, s, o);
        if (lane == 0) s_base = s;
    }
    __syncthreads();
    if (nvalid) g_woff[node] = s_base + ex_local;
    grid_sync(2);

    // ================= P3: atomic-free scatter (x2 unroll) + bnode + gemm1 =
    for (int i = gth; i < NE2; i += 2 * GT) {
        int s0, s1, d0, d1;
        if (f64) {
            int4 sv = ((const int4*)ei)[i];       s0 = sv.x; s1 = sv.z;
            int4 dv = ((const int4*)ei)[NE2 + i]; d0 = dv.x; d1 = dv.z;
        } else {
            int2 sv = ((const int2*)ei)[i];       s0 = sv.x; s1 = sv.y;
            int2 dv = ((const int2*)ei)[NE2 + i]; d0 = dv.x; d1 = dv.y;
        }
        int2 rkA = ((const int2*)g_erank)[i];
        int i2 = i + GT;
        bool have2 = (i2 < NE2);
        int s2 = 0, s3 = 0, d2 = 0, d3 = 0;
        int2 rkB = make_int2(0, 0);
        if (have2) {
            if (f64) {
                int4 sv = ((const int4*)ei)[i2];       s2 = sv.x; s3 = sv.z;
                int4 dv = ((const int4*)ei)[NE2 + i2]; d2 = dv.x; d3 = dv.z;
            } else {
                int2 sv = ((const int2*)ei)[i2];       s2 = sv.x; s3 = sv.y;
                int2 dv = ((const int2*)ei)[NE2 + i2]; d2 = dv.x; d3 = dv.y;
            }
            rkB = ((const int2*)g_erank)[i2];
        }
        int w0 = g_woff[d0];
        int w1 = g_woff[d1];
        int w2 = have2 ? g_woff[d2] : 0;
        int w3 = have2 ? g_woff[d3] : 0;
        g_csrc[w0 + rkA.x] = s0;
        g_csrc[w1 + rkA.y] = s1;
        if (have2) {
            g_csrc[w2 + rkB.x] = s2;
            g_csrc[w3 + rkB.y] = s3;
        }
    }
    for (int i = gth; i < NUM_N; i += GT) {
        g_bnode[g_boff[g_batch[i]] + g_nrank[i]] = i;
    }
    for (int i = tid; i < 512; i += TPB) w1s[i] = ((const ulonglong2*)W1)[i];
    __syncthreads();
    {   // gemm1: f32x2 packed FMAs, double-buffered x row, fp16 output
        int w = gw;
        float4 xv = make_float4(0.f, 0.f, 0.f, 0.f);
        if (w < NUM_N) xv = ((const float4*)x)[(size_t)w * 32 + lane];
        for (; w < NUM_N; w += NWARP) {
            int wn = w + NWARP;
            float4 xvN = make_float4(0.f, 0.f, 0.f, 0.f);
            if (wn < NUM_N) xvN = ((const float4*)x)[(size_t)wn * 32 + lane];
            float dvd = g_dinv[w];
            unsigned long long A[8];
            #pragma unroll
            for (int j = 0; j < 8; j++) A[j] = 0ull;
            {
                float xs[4] = {xv.x, xv.y, xv.z, xv.w};
                int kb4 = lane * 16;
                #pragma unroll
                for (int kk = 0; kk < 4; kk++) {
                    unsigned long long cp = pack2(xs[kk]);
                    #pragma unroll
                    for (int q = 0; q < 4; q++) {
                        ulonglong2 wv = w1s[kb4 + kk * 4 + q];
                        A[2*q+0] = fma2(cp, wv.x, A[2*q+0]);
                        A[2*q+1] = fma2(cp, wv.y, A[2*q+1]);
                    }
                }
            }
            float a[16];
            #pragma unroll
            for (int p = 0; p < 8; p++) unpack2(A[p], a[2*p], a[2*p+1]);
            {   // halving butterfly
                float t[16];
                #pragma unroll
                for (int i = 0; i < 16; i++) t[i] = __shfl_xor_sync(~0u, a[i], 16);
                if ((lane & 16) == 0) {
                    #pragma unroll
                    for (int i = 0; i < 8; i++) a[i] += t[i]; }
                else {
                    #pragma unroll
                    for (int i = 0; i < 8; i++) a[i] = a[i+8] + t[i+8]; }
            }
            {
                float t[8];
                #pragma unroll
                for (int i = 0; i < 8; i++) t[i] = __shfl_xor_sync(~0u, a[i], 8);
                if ((lane & 8) == 0) {
                    #pragma unroll
                    for (int i = 0; i < 4; i++) a[i] += t[i]; }
                else {
                    #pragma unroll
                    for (int i = 0; i < 4; i++) a[i] = a[i+4] + t[i+4]; }
            }
            {
                float t[4];
                #pragma unroll
                for (int i = 0; i < 4; i++) t[i] = __shfl_xor_sync(~0u, a[i], 4);
                if ((lane & 4) == 0) { a[0] += t[0]; a[1] += t[1]; }
                else                 { a[0] = a[2] + t[2]; a[1] = a[3] + t[3]; }
            }
            {
                float t0 = __shfl_xor_sync(~0u, a[0], 2);
                float t1 = __shfl_xor_sync(~0u, a[1], 2);
                if ((lane & 2) == 0) a[0] += t0; else a[0] = a[1] + t1;
            }
            a[0] += __shfl_xor_sync(~0u, a[0], 1);
            float vres = a[0] * dvd;
            float vhi = __shfl_down_sync(~0u, vres, 2);
            if ((lane & 3) == 0)
                ((__half2*)g_h1h)[(size_t)w * 8 + (lane >> 2)] =
                    __floats2half2_rn(vres, vhi);
            xv = xvN;
        }
    }
    grid_sync(3);

    // ===== P4: prop1 — two nodes/warp, 16 edges in flight per half =========
    if (bid == GRID - 1 && tid < NUM_G) g_pcnt[tid] = 0;
    {
        const int sub  = lane & 3;
        const int grp  = (lane >> 2) & 3;    // edge slot 0..3 within half
        const int nsel = lane >> 4;          // node select 0/1
        const int stride = 2 * NWARP;
        const __half2 h2z = __floats2half2_rn(0.f, 0.f);
        int w = gw * 2;
        int dgC, stC, dgN = 0, stN = 0;
        int s0C = 0, s1C = 0, s2C = 0, s3C = 0;
        {
            int myn = w + nsel;
            dgC = g_deg[myn]; stC = g_woff[myn];
            if (grp      < dgC) s0C = g_csrc[stC + grp];
            if (grp + 4  < dgC) s1C = g_csrc[stC + grp + 4];
            if (grp + 8  < dgC) s2C = g_csrc[stC + grp + 8];
            if (grp + 12 < dgC) s3C = g_csrc[stC + grp + 12];
            int wn = myn + stride;
            if (wn < NUM_N) { dgN = g_deg[wn]; stN = g_woff[wn]; }
        }
        for (; w < NUM_N; w += stride) {
            int curn = w + nsel;
            int wn2 = curn + 2 * stride;
            int dgN2 = 0, stN2 = 0;
            if (wn2 < NUM_N) { dgN2 = g_deg[wn2]; stN2 = g_woff[wn2]; }
            int s0N = 0, s1N = 0, s2N = 0, s3N = 0;
            if (grp      < dgN) s0N = g_csrc[stN + grp];
            if (grp + 4  < dgN) s1N = g_csrc[stN + grp + 4];
            if (grp + 8  < dgN) s2N = g_csrc[stN + grp + 8];
            if (grp + 12 < dgN) s3N = g_csrc[stN + grp + 12];
            __half2 m0 = h2z, m1 = h2z, n0 = h2z, n1 = h2z;
            __half2 o0 = h2z, o1 = h2z, p0 = h2z, p1 = h2z;
            if (grp      < dgC) gatherh2(g_h1h, s0C, sub, m0, m1);
            if (grp + 4  < dgC) gatherh2(g_h1h, s1C, sub, n0, n1);
            if (grp + 8  < dgC) gatherh2(g_h1h, s2C, sub, o0, o1);
            if (grp + 12 < dgC) gatherh2(g_h1h, s3C, sub, p0, p1);
            for (int e = grp + 16; e < dgC; e += 16) {
                int t0 = g_csrc[stC + e];
                int t1 = (e + 4  < dgC) ? g_csrc[stC + e + 4]  : 0;
                int t2 = (e + 8  < dgC) ? g_csrc[stC + e + 8]  : 0;
                int t3 = (e + 12 < dgC) ? g_csrc[stC + e + 12] : 0;
                gatherh2(g_h1h, t0, sub, m0, m1);
                if (e + 4  < dgC) gatherh2(g_h1h, t1, sub, n0, n1);
                if (e + 8  < dgC) gatherh2(g_h1h, t2, sub, o0, o1);
                if (e + 12 < dgC) gatherh2(g_h1h, t3, sub, p0, p1);
            }
            float2 fm0 = __half22float2(m0), fm1 = __half22float2(m1);
            float2 fn0 = __half22float2(n0), fn1 = __half22float2(n1);
            float2 fo0 = __half22float2(o0), fo1 = __half22float2(o1);
            float2 fp0 = __half22float2(p0), fp1 = __half22float2(p1);
            float ax = (fm0.x + fn0.x) + (fo0.x + fp0.x);
            float ay = (fm0.y + fn0.y) + (fo0.y + fp0.y);
            float az = (fm1.x + fn1.x) + (fo1.x + fp1.x);
            float aw = (fm1.y + fn1.y) + (fo1.y + fp1.y);
            #pragma unroll
            for (int o = 4; o < 16; o <<= 1) {
                ax += __shfl_xor_sync(~0u, ax, o);
                ay += __shfl_xor_sync(~0u, ay, o);
                az += __shfl_xor_sync(~0u, az, o);
                aw += __shfl_xor_sync(~0u, aw, o);
            }
            if ((lane & 12) == 0) {
                float dvd = g_dinv[curn];
                float hx, hy, hz, hw;
                read16h(g_h1h, curn, sub, hx, hy, hz, hw);
                float4 bv = ((const float4*)b1)[sub];
                float ox = fmaxf(fmaf(dvd, ax + hx, bv.x), 0.f) * dvd;
                float oy = fmaxf(fmaf(dvd, ay + hy, bv.y), 0.f) * dvd;
                float oz = fmaxf(fmaf(dvd, az + hz, bv.z), 0.f) * dvd;
                float ow = fmaxf(fmaf(dvd, aw + hw, bv.w), 0.f) * dvd;
                uint2 u;
                *(__half2*)&u.x = __floats2half2_rn(ox, oy);
                *(__half2*)&u.y = __floats2half2_rn(oz, ow);
                ((uint2*)g_qh)[(size_t)curn * 4 + sub] = u;
            }
            dgC = dgN; stC = stN; dgN = dgN2; stN = stN2;
            s0C = s0N; s1C = s1N; s2C = s2N; s3C = s3N;
        }
    }
    grid_sync(4);

    // ===== P5: prop2 — two nodes/warp, 16 edges in flight per half =========
    {
        const int sub  = lane & 3;
        const int grp  = (lane >> 2) & 3;
        const int nsel = lane >> 4;
        const int stride = 2 * NWARP;
        const __half2 h2z = __floats2half2_rn(0.f, 0.f);
        int w = gw * 2;
        int dgC, stC, dgN = 0, stN = 0;
        int s0C = 0, s1C = 0, s2C = 0, s3C = 0;
        {
            int myn = w + nsel;
            dgC = g_deg[myn]; stC = g_woff[myn];
            if (grp      < dgC) s0C = g_csrc[stC + grp];
            if (grp + 4  < dgC) s1C = g_csrc[stC + grp + 4];
            if (grp + 8  < dgC) s2C = g_csrc[stC + grp + 8];
            if (grp + 12 < dgC) s3C = g_csrc[stC + grp + 12];
            int wn = myn + stride;
            if (wn < NUM_N) { dgN = g_deg[wn]; stN = g_woff[wn]; }
        }
        for (; w < NUM_N; w += stride) {
            int curn = w + nsel;
            int wn2 = curn + 2 * stride;
            int dgN2 = 0, stN2 = 0;
            if (wn2 < NUM_N) { dgN2 = g_deg[wn2]; stN2 = g_woff[wn2]; }
            int s0N = 0, s1N = 0, s2N = 0, s3N = 0;
            if (grp      < dgN) s0N = g_csrc[stN + grp];
            if (grp + 4  < dgN) s1N = g_csrc[stN + grp + 4];
            if (grp + 8  < dgN) s2N = g_csrc[stN + grp + 8];
            if (grp + 12 < dgN) s3N = g_csrc[stN + grp + 12];
            __half2 m0 = h2z, m1 = h2z, n0 = h2z, n1 = h2z;
            __half2 o0 = h2z, o1 = h2z, p0 = h2z, p1 = h2z;
            if (grp      < dgC) gatherh2(g_qh, s0C, sub, m0, m1);
            if (grp + 4  < dgC) gatherh2(g_qh, s1C, sub, n0, n1);
            if (grp + 8  < dgC) gatherh2(g_qh, s2C, sub, o0, o1);
            if (grp + 12 < dgC) gatherh2(g_qh, s3C, sub, p0, p1);
            for (int e = grp + 16; e < dgC; e += 16) {
                int t0 = g_csrc[stC + e];
                int t1 = (e + 4  < dgC) ? g_csrc[stC + e + 4]  : 0;
                int t2 = (e + 8  < dgC) ? g_csrc[stC + e + 8]  : 0;
                int t3 = (e + 12 < dgC) ? g_csrc[stC + e + 12] : 0;
                gatherh2(g_qh, t0, sub, m0, m1);
                if (e + 4  < dgC) gatherh2(g_qh, t1, sub, n0, n1);
                if (e + 8  < dgC) gatherh2(g_qh, t2, sub, o0, o1);
                if (e + 12 < dgC) gatherh2(g_qh, t3, sub, p0, p1);
            }
            float2 fm0 = __half22float2(m0), fm1 = __half22float2(m1);
            float2 fn0 = __half22float2(n0), fn1 = __half22float2(n1);
            float2 fo0 = __half22float2(o0), fo1 = __half22float2(o1);
            float2 fp0 = __half22float2(p0), fp1 = __half22float2(p1);
            float ax = (fm0.x + fn0.x) + (fo0.x + fp0.x);
            float ay = (fm0.y + fn0.y) + (fo0.y + fp0.y);
            float az = (fm1.x + fn1.x) + (fo1.x + fp1.x);
            float aw = (fm1.y + fn1.y) + (fo1.y + fp1.y);
            #pragma unroll
            for (int o = 4; o < 16; o <<= 1) {
                ax += __shfl_xor_sync(~0u, ax, o);
                ay += __shfl_xor_sync(~0u, ay, o);
                az += __shfl_xor_sync(~0u, az, o);
                aw += __shfl_xor_sync(~0u, aw, o);
            }
            if ((lane & 12) == 0) {
                float dvd = g_dinv[curn];
                float qx, qy, qz, qw;
                read16h(g_qh, curn, sub, qx, qy, qz, qw);
                float4 o;
                o.x = dvd * (ax + qx); o.y = dvd * (ay + qy);
                o.z = dvd * (az + qz); o.w = dvd * (aw + qw);
                ((float4*)g_r)[(size_t)curn * 4 + sub] = o;
            }
            dgC = dgN; stC = stN; dgN = dgN2; stN = stN2;
            s0C = s0N; s1C = s1N; s2C = s2N; s3C = s3N;
        }
    }
    grid_sync(5);

    // ================= P6: pool + gemm2 + mlp (blocks 0..127) ==============
    if (bid < NUM_G) {
        for (int i = tid; i < 512; i += TPB) w2s[i] = ((const float4*)W2)[i];
        __syncthreads();
        const int g = bid;
        const int cnt = g_pcnt2[g];
        const int start = g_boff[g];
        float4 bv = ((const float4*)b2)[lane];
        float4 sum = make_float4(0.f, 0.f, 0.f, 0.f);
        int i = wid;
        float rvN = 0.f;
        if (i < cnt) {
            int n = g_bnode[start + i];
            rvN = (lane < 16) ? g_r[n * 16 + lane] : 0.f;
        }
        for (; i < cnt; i += 32) {
            float rv = rvN;
            int in2 = i + 32;
            if (in2 < cnt) {
                int n2 = g_bnode[start + in2];
                rvN = (lane < 16) ? g_r[n2 * 16 + lane] : 0.f;
            }
            float4 acc = bv;
            #pragma unroll
            for (int k = 0; k < 16; k++) {
                float s = __shfl_sync(~0u, rv, k);
                float4 wv = w2s[k * 32 + lane];
                acc.x = fmaf(s, wv.x, acc.x); acc.y = fmaf(s, wv.y, acc.y);
                acc.z = fmaf(s, wv.z, acc.z); acc.w = fmaf(s, wv.w, acc.w);
            }
            sum.x += fmaxf(acc.x, 0.f); sum.y += fmaxf(acc.y, 0.f);
            sum.z += fmaxf(acc.z, 0.f); sum.w += fmaxf(acc.w, 0.f);
        }
        red[wid * 32 + lane] = sum;
        __syncthreads();
        if (tid < 32) {
            float4 tot = red[tid];
            #pragma unroll
            for (int w2 = 1; w2 < 32; w2++) {
                float4 vv = red[w2 * 32 + tid];
                tot.x += vv.x; tot.y += vv.y; tot.z += vv.z; tot.w += vv.w;
            }
            float inv = 1.f / fmaxf((float)cnt, 1.f);
            ps[tid * 4 + 0] = tot.x * inv; ps[tid * 4 + 1] = tot.y * inv;
            ps[tid * 4 + 2] = tot.z * inv; ps[tid * 4 + 3] = tot.w * inv;
        }
        __syncthreads();
        if (tid < 128) {
            float acc = Lb1[tid];
            #pragma unroll 8
            for (int k = 0; k < 128; k++) acc = fmaf(ps[k], LW1[k * 128 + tid], acc);
            z1[tid] = fmaxf(acc, 0.f);
        }
        __syncthreads();
        if (tid < 2) {
            float a = Lb2[tid];
            for (int k = 0; k < 128; k++) a = fmaf(z1[k], LW2[k * 2 + tid], a);
            z2[tid] = a;
        }
        __syncthreads();
        if (tid == 0) {
            float m = fmaxf(z2[0], z2[1]);
            float lse = m + logf(expf(z2[0] - m) + expf(z2[1] - m));
            out[g * 2 + 0] = z2[0] - lse;
            out[g * 2 + 1] = z2[1] - lse;
        }
    } else {
        for (int i = (bid - NUM_G) * TPB + tid; i < NUM_N; i += (GRID - NUM_G) * TPB)
            g_deg[i] = 0;
    }
}

// -------- launch --------
extern "C" void kernel_launch(void* const* d_in, const int* in_sizes, int n_in,
                              void* d_out, int out_size) {
    const float* x   = (const float*)d_in[0];
    const void*  ei  = d_in[1];
    const void*  bat = d_in[2];
    const float* W1  = (const float*)d_in[3];
    const float* b1  = (const float*)d_in[4];
    const float* W2  = (const float*)d_in[5];
    const float* b2  = (const float*)d_in[6];
    const float* LW1 = (const float*)d_in[7];
    const float* Lb1 = (const float*)d_in[8];
    const float* LW2 = (const float*)d_in[9];
    const float* Lb2 = (const float*)d_in[10];
    float* out = (float*)d_out;

    mega_kernel<<<GRID, TPB>>>(x, ei, bat, W1, b1, W2, b2,
                               LW1, Lb1, LW2, Lb2, out);
}

// round 15
// speedup vs baseline: 1.4674x; 1.0075x over previous
#include <cuda_runtime.h>
#include <cuda_fp16.h>
#include <math.h>

#define NUM_N 100000
#define NUM_E 1600000
#define NUM_G 128
#define D_IN 128

#define GRID  148
#define TPB   1024
#define GT    (GRID * TPB)        // 151552 threads
#define NWARP (GT / 32)           // 4736 warps
#define CHUNK 676                 // 148*676 >= NUM_N
#define NE2   (NUM_E / 2)         // 800000 edge pairs

// -------- device scratch (statics start zeroed) ----------------------------
__device__ int    g_bar[8];
__device__ int    g_batch[NUM_N];
__device__ int    g_deg[NUM_N];      // re-zeroed for replay in P6
__device__ float  g_dinv[NUM_N];
__device__ int    g_woff[NUM_N];     // pristine CSR start offsets
__device__ int    g_erank[NUM_E];    // per-edge rank within dst bucket
__device__ int    g_nrank[NUM_N];    // per-node rank within graph bucket
__device__ int    g_csrc[NUM_E];
__device__ int    g_bsum[GRID];
__device__ int    g_pcnt[NUM_G];     // re-zeroed in P4
__device__ int    g_pcnt2[NUM_G];    // pristine copy for pool
__device__ int    g_boff[NUM_G];     // pristine batch CSR offsets
__device__ int    g_bnode[NUM_N];
__device__ __half g_h1h[NUM_N * 16];
__device__ __half g_qh [NUM_N * 16];
__device__ float  g_r  [NUM_N * 16];

// -------- software grid barrier -------------------------------------------
__device__ __forceinline__ void grid_sync(int j) {
    __syncthreads();
    __threadfence();
    if (threadIdx.x == 0) {
        if (atomicAdd(&g_bar[j], 1) == GRID - 1) {
            atomicExch(&g_bar[(j + 4) % 6], 0);
        } else {
            while (*((volatile int*)&g_bar[j]) < GRID) { }
        }
    }
    __syncthreads();
    __threadfence();
}

// fp16 gather + HADD2 accumulate
__device__ __forceinline__ void gatherh2(const __half* base, int s, int sub,
                                         __half2& a0, __half2& a1) {
    uint2 u = ((const uint2*)(base))[s * 4 + sub];
    a0 = __hadd2(a0, *(__half2*)&u.x);
    a1 = __hadd2(a1, *(__half2*)&u.y);
}

// fp32 read of one node's 4-half chunk
__device__ __forceinline__ void read16h(const __half* base, int s, int sub,
                                        float& x0, float& y0, float& z0, float& w0) {
    uint2 u = ((const uint2*)(base))[s * 4 + sub];
    float2 f0 = __half22float2(*(__half2*)&u.x);
    float2 f1 = __half22float2(*(__half2*)&u.y);
    x0 = f0.x; y0 = f0.y; z0 = f1.x; w0 = f1.y;
}

// packed f32x2 helpers
__device__ __forceinline__ unsigned long long fma2(unsigned long long c,
                                                   unsigned long long w,
                                                   unsigned long long a) {
    unsigned long long d;
    asm("fma.rn.f32x2 %0, %1, %2, %3;" : "=l"(d) : "l"(c), "l"(w), "l"(a));
    return d;
}
__device__ __forceinline__ unsigned long long pack2(float c) {
    unsigned long long d;
    asm("mov.b64 %0, {%1, %1};" : "=l"(d) : "f"(c));
    return d;
}
__device__ __forceinline__ void unpack2(unsigned long long p, float& lo, float& hi) {
    asm("mov.b64 {%0, %1}, %2;" : "=f"(lo), "=f"(hi) : "l"(p));
}

__global__ __launch_bounds__(TPB, 1) void mega_kernel(
    const float* __restrict__ x, const void* ei, const void* bat,
    const float* __restrict__ W1, const float* __restrict__ b1,
    const float* __restrict__ W2, const float* __restrict__ b2,
    const float* __restrict__ LW1, const float* __restrict__ Lb1,
    const float* __restrict__ LW2, const float* __restrict__ Lb2,
    float* __restrict__ out)
{
    __shared__ ulonglong2 w1s[512];   // W1 as f32x2 pairs
    __shared__ float4 w2s[512];
    __shared__ float4 red[1024];
    __shared__ int    wsum[32];
    __shared__ int    s_i32, s_base;
    __shared__ float  ps[128], z1[128], z2[2];

    const int tid  = threadIdx.x, bid = blockIdx.x;
    const int lane = tid & 31,    wid = tid >> 5;
    const int gth  = bid * TPB + tid;
    const int gw   = gth >> 5;

    // ---- detect int64 vs int32 index layout ----
    if (tid == 0) s_i32 = 0;
    __syncthreads();
    if (tid < 64) {
        long long v = ((const long long*)ei)[(size_t)tid * (NUM_E / 64)];
        if (v < 0 || v >= (long long)NUM_N) s_i32 = 1;
    }
    __syncthreads();
    const bool f64 = (s_i32 == 0);

    // ===== P0: histograms + rank capture (x2 unroll, 4 atomics in flight) ==
    for (int i = gth; i < NE2; i += 2 * GT) {
        int d0, d1;
        if (f64) { int4 v = ((const int4*)ei)[NE2 + i]; d0 = v.x; d1 = v.z; }
        else     { int2 v = ((const int2*)ei)[NE2 + i]; d0 = v.x; d1 = v.y; }
        int i2 = i + GT;
        bool have2 = (i2 < NE2);
        int d2 = 0, d3 = 0;
        if (have2) {
            if (f64) { int4 v = ((const int4*)ei)[NE2 + i2]; d2 = v.x; d3 = v.z; }
            else     { int2 v = ((const int2*)ei)[NE2 + i2]; d2 = v.x; d3 = v.y; }
        }
        int r0 = atomicAdd(&g_deg[d0], 1);
        int r1 = atomicAdd(&g_deg[d1], 1);
        int r2 = 0, r3 = 0;
        if (have2) {
            r2 = atomicAdd(&g_deg[d2], 1);
            r3 = atomicAdd(&g_deg[d3], 1);
        }
        g_erank[2 * i]     = r0;     // scalar stores: each waits only on its own return
        g_erank[2 * i + 1] = r1;
        if (have2) {
            g_erank[2 * i2]     = r2;
            g_erank[2 * i2 + 1] = r3;
        }
    }
    for (int i = gth; i < NUM_N; i += 2 * GT) {
        int b0v = f64 ? (int)((const long long*)bat)[i] : ((const int*)bat)[i];
        int i2 = i + GT;
        bool have2 = (i2 < NUM_N);
        int b1v = 0;
        if (have2) b1v = f64 ? (int)((const long long*)bat)[i2] : ((const int*)bat)[i2];
        g_batch[i] = b0v;
        int ra = atomicAdd(&g_pcnt[b0v], 1);
        int rb = 0;
        if (have2) { g_batch[i2] = b1v; rb = atomicAdd(&g_pcnt[b1v], 1); }
        g_nrank[i] = ra;
        if (have2) g_nrank[i2] = rb;
    }
    grid_sync(0);

    // ================= P1: block-local scan of deg (+dinv, batch scan) =====
    const int node = bid * CHUNK + tid;
    const bool nvalid = (tid < CHUNK) && (node < NUM_N);
    int deg = nvalid ? g_deg[node] : 0;
    int v = deg;
    #pragma unroll
    for (int o = 1; o < 32; o <<= 1) {
        int n = __shfl_up_sync(~0u, v, o);
        if (lane >= o) v += n;
    }
    if (lane == 31) wsum[wid] = v;
    __syncthreads();
    if (wid == 0) {
        int wv = wsum[lane];
        #pragma unroll
        for (int o = 1; o < 32; o <<= 1) {
            int n = __shfl_up_sync(~0u, wv, o);
            if (lane >= o) wv += n;
        }
        wsum[lane] = wv;
    }
    __syncthreads();
    const int ex_local = (wid ? wsum[wid - 1] : 0) + v - deg;
    if (tid == 0) g_bsum[bid] = wsum[31];
    if (nvalid) g_dinv[node] = rsqrtf((float)deg + 1.f);
    if (bid == 0 && wid == 31) {
        int p0 = g_pcnt[lane*4+0], p1 = g_pcnt[lane*4+1];
        int p2 = g_pcnt[lane*4+2], p3 = g_pcnt[lane*4+3];
        int t1 = p0 + p1, t2 = t1 + p2, t3 = t2 + p3;
        int vv = t3;
        #pragma unroll
        for (int o = 1; o < 32; o <<= 1) {
            int n = __shfl_up_sync(~0u, vv, o);
            if (lane >= o) vv += n;
        }
        int exb = vv - t3;
        g_boff[lane*4+0] = exb;
        g_boff[lane*4+1] = exb + p0;
        g_boff[lane*4+2] = exb + t1;
        g_boff[lane*4+3] = exb + t2;
        g_pcnt2[lane*4+0] = p0; g_pcnt2[lane*4+1] = p1;
        g_pcnt2[lane*4+2] = p2; g_pcnt2[lane*4+3] = p3;
    }
    grid_sync(1);

    // ================= P2: per-block global base, write woff ===============
    if (wid == 0) {
        int s = 0;
        for (int i = lane; i < bid; i += 32) s += g_bsum[i];
        #pragma unroll
        for (int o = 16; o; o >>= 1) s += __shfl_xor_sync(~0u, s, o);
        if (lane == 0) s_base = s;
    }
    __syncthreads();
    if (nvalid) g_woff[node] = s_base + ex_local;
    grid_sync(2);

    // ================= P3: atomic-free scatter (x2 unroll) + bnode + gemm1 =
    for (int i = gth; i < NE2; i += 2 * GT) {
        int s0, s1, d0, d1;
        if (f64) {
            int4 sv = ((const int4*)ei)[i];       s0 = sv.x; s1 = sv.z;
            int4 dv = ((const int4*)ei)[NE2 + i]; d0 = dv.x; d1 = dv.z;
        } else {
            int2 sv = ((const int2*)ei)[i];       s0 = sv.x; s1 = sv.y;
            int2 dv = ((const int2*)ei)[NE2 + i]; d0 = dv.x; d1 = dv.y;
        }
        int2 rkA = ((const int2*)g_erank)[i];
        int i2 = i + GT;
        bool have2 = (i2 < NE2);
        int s2 = 0, s3 = 0, d2 = 0, d3 = 0;
        int2 rkB = make_int2(0, 0);
        if (have2) {
            if (f64) {
                int4 sv = ((const int4*)ei)[i2];       s2 = sv.x; s3 = sv.z;
                int4 dv = ((const int4*)ei)[NE2 + i2]; d2 = dv.x; d3 = dv.z;
            } else {
                int2 sv = ((const int2*)ei)[i2];       s2 = sv.x; s3 = sv.y;
                int2 dv = ((const int2*)ei)[NE2 + i2]; d2 = dv.x; d3 = dv.y;
            }
            rkB = ((const int2*)g_erank)[i2];
        }
        int w0 = g_woff[d0];
        int w1 = g_woff[d1];
        int w2 = have2 ? g_woff[d2] : 0;
        int w3 = have2 ? g_woff[d3] : 0;
        g_csrc[w0 + rkA.x] = s0;
        g_csrc[w1 + rkA.y] = s1;
        if (have2) {
            g_csrc[w2 + rkB.x] = s2;
            g_csrc[w3 + rkB.y] = s3;
        }
    }
    for (int i = gth; i < NUM_N; i += GT) {
        g_bnode[g_boff[g_batch[i]] + g_nrank[i]] = i;
    }
    for (int i = tid; i < 512; i += TPB) w1s[i] = ((const ulonglong2*)W1)[i];
    __syncthreads();
    {   // gemm1: f32x2 packed FMAs, double-buffered x row, fp16 output
        int w = gw;
        float4 xv = make_float4(0.f, 0.f, 0.f, 0.f);
        if (w < NUM_N) xv = ((const float4*)x)[(size_t)w * 32 + lane];
        for (; w < NUM_N; w += NWARP) {
            int wn = w + NWARP;
            float4 xvN = make_float4(0.f, 0.f, 0.f, 0.f);
            if (wn < NUM_N) xvN = ((const float4*)x)[(size_t)wn * 32 + lane];
            float dvd = g_dinv[w];
            unsigned long long A[8];
            #pragma unroll
            for (int j = 0; j < 8; j++) A[j] = 0ull;
            {
                float xs[4] = {xv.x, xv.y, xv.z, xv.w};
                int kb4 = lane * 16;
                #pragma unroll
                for (int kk = 0; kk < 4; kk++) {
                    unsigned long long cp = pack2(xs[kk]);
                    #pragma unroll
                    for (int q = 0; q < 4; q++) {
                        ulonglong2 wv = w1s[kb4 + kk * 4 + q];
                        A[2*q+0] = fma2(cp, wv.x, A[2*q+0]);
                        A[2*q+1] = fma2(cp, wv.y, A[2*q+1]);
                    }
                }
            }
            float a[16];
            #pragma unroll
            for (int p = 0; p < 8; p++) unpack2(A[p], a[2*p], a[2*p+1]);
            {   // halving butterfly
                float t[16];
                #pragma unroll
                for (int i = 0; i < 16; i++) t[i] = __shfl_xor_sync(~0u, a[i], 16);
                if ((lane & 16) == 0) {
                    #pragma unroll
                    for (int i = 0; i < 8; i++) a[i] += t[i]; }
                else {
                    #pragma unroll
                    for (int i = 0; i < 8; i++) a[i] = a[i+8] + t[i+8]; }
            }
            {
                float t[8];
                #pragma unroll
                for (int i = 0; i < 8; i++) t[i] = __shfl_xor_sync(~0u, a[i], 8);
                if ((lane & 8) == 0) {
                    #pragma unroll
                    for (int i = 0; i < 4; i++) a[i] += t[i]; }
                else {
                    #pragma unroll
                    for (int i = 0; i < 4; i++) a[i] = a[i+4] + t[i+4]; }
            }
            {
                float t[4];
                #pragma unroll
                for (int i = 0; i < 4; i++) t[i] = __shfl_xor_sync(~0u, a[i], 4);
                if ((lane & 4) == 0) { a[0] += t[0]; a[1] += t[1]; }
                else                 { a[0] = a[2] + t[2]; a[1] = a[3] + t[3]; }
            }
            {
                float t0 = __shfl_xor_sync(~0u, a[0], 2);
                float t1 = __shfl_xor_sync(~0u, a[1], 2);
                if ((lane & 2) == 0) a[0] += t0; else a[0] = a[1] + t1;
            }
            a[0] += __shfl_xor_sync(~0u, a[0], 1);
            float vres = a[0] * dvd;
            float vhi = __shfl_down_sync(~0u, vres, 2);
            if ((lane & 3) == 0)
                ((__half2*)g_h1h)[(size_t)w * 8 + (lane >> 2)] =
                    __floats2half2_rn(vres, vhi);
            xv = xvN;
        }
    }
    grid_sync(3);

    // ===== P4: prop1 — two nodes/warp, 16 edges in flight per half =========
    if (bid == GRID - 1 && tid < NUM_G) g_pcnt[tid] = 0;
    {
        const int sub  = lane & 3;
        const int grp  = (lane >> 2) & 3;    // edge slot 0..3 within half
        const int nsel = lane >> 4;          // node select 0/1
        const int stride = 2 * NWARP;
        const __half2 h2z = __floats2half2_rn(0.f, 0.f);
        int w = gw * 2;
        int dgC, stC, dgN = 0, stN = 0;
        int s0C = 0, s1C = 0, s2C = 0, s3C = 0;
        {
            int myn = w + nsel;
            dgC = g_deg[myn]; stC = g_woff[myn];
            if (grp      < dgC) s0C = g_csrc[stC + grp];
            if (grp + 4  < dgC) s1C = g_csrc[stC + grp + 4];
            if (grp + 8  < dgC) s2C = g_csrc[stC + grp + 8];
            if (grp + 12 < dgC) s3C = g_csrc[stC + grp + 12];
            int wn = myn + stride;
            if (wn < NUM_N) { dgN = g_deg[wn]; stN = g_woff[wn]; }
        }
        for (; w < NUM_N; w += stride) {
            int curn = w + nsel;
            int wn2 = curn + 2 * stride;
            int dgN2 = 0, stN2 = 0;
            if (wn2 < NUM_N) { dgN2 = g_deg[wn2]; stN2 = g_woff[wn2]; }
            int s0N = 0, s1N = 0, s2N = 0, s3N = 0;
            if (grp      < dgN) s0N = g_csrc[stN + grp];
            if (grp + 4  < dgN) s1N = g_csrc[stN + grp + 4];
            if (grp + 8  < dgN) s2N = g_csrc[stN + grp + 8];
            if (grp + 12 < dgN) s3N = g_csrc[stN + grp + 12];
            __half2 m0 = h2z, m1 = h2z, n0 = h2z, n1 = h2z;
            __half2 o0 = h2z, o1 = h2z, p0 = h2z, p1 = h2z;
            if (grp      < dgC) gatherh2(g_h1h, s0C, sub, m0, m1);
            if (grp + 4  < dgC) gatherh2(g_h1h, s1C, sub, n0, n1);
            if (grp + 8  < dgC) gatherh2(g_h1h, s2C, sub, o0, o1);
            if (grp + 12 < dgC) gatherh2(g_h1h, s3C, sub, p0, p1);
            for (int e = grp + 16; e < dgC; e += 16) {
                int t0 = g_csrc[stC + e];
                int t1 = (e + 4  < dgC) ? g_csrc[stC + e + 4]  : 0;
                int t2 = (e + 8  < dgC) ? g_csrc[stC + e + 8]  : 0;
                int t3 = (e + 12 < dgC) ? g_csrc[stC + e + 12] : 0;
                gatherh2(g_h1h, t0, sub, m0, m1);
                if (e + 4  < dgC) gatherh2(g_h1h, t1, sub, n0, n1);
                if (e + 8  < dgC) gatherh2(g_h1h, t2, sub, o0, o1);
                if (e + 12 < dgC) gatherh2(g_h1h, t3, sub, p0, p1);
            }
            float2 fm0 = __half22float2(m0), fm1 = __half22float2(m1);
            float2 fn0 = __half22float2(n0), fn1 = __half22float2(n1);
            float2 fo0 = __half22float2(o0), fo1 = __half22float2(o1);
            float2 fp0 = __half22float2(p0), fp1 = __half22float2(p1);
            float ax = (fm0.x + fn0.x) + (fo0.x + fp0.x);
            float ay = (fm0.y + fn0.y) + (fo0.y + fp0.y);
            float az = (fm1.x + fn1.x) + (fo1.x + fp1.x);
            float aw = (fm1.y + fn1.y) + (fo1.y + fp1.y);
            #pragma unroll
            for (int o = 4; o < 16; o <<= 1) {
                ax += __shfl_xor_sync(~0u, ax, o);
                ay += __shfl_xor_sync(~0u, ay, o);
                az += __shfl_xor_sync(~0u, az, o);
                aw += __shfl_xor_sync(~0u, aw, o);
            }
            if ((lane & 12) == 0) {
                float dvd = g_dinv[curn];
                float hx, hy, hz, hw;
                read16h(g_h1h, curn, sub, hx, hy, hz, hw);
                float4 bv = ((const float4*)b1)[sub];
                float ox = fmaxf(fmaf(dvd, ax + hx, bv.x), 0.f) * dvd;
                float oy = fmaxf(fmaf(dvd, ay + hy, bv.y), 0.f) * dvd;
                float oz = fmaxf(fmaf(dvd, az + hz, bv.z), 0.f) * dvd;
                float ow = fmaxf(fmaf(dvd, aw + hw, bv.w), 0.f) * dvd;
                uint2 u;
                *(__half2*)&u.x = __floats2half2_rn(ox, oy);
                *(__half2*)&u.y = __floats2half2_rn(oz, ow);
                ((uint2*)g_qh)[(size_t)curn * 4 + sub] = u;
            }
            dgC = dgN; stC = stN; dgN = dgN2; stN = stN2;
            s0C = s0N; s1C = s1N; s2C = s2N; s3C = s3N;
        }
    }
    grid_sync(4);

    // ===== P5: prop2 — two nodes/warp, 16 edges in flight per half =========
    {
        const int sub  = lane & 3;
        const int grp  = (lane >> 2) & 3;
        const int nsel = lane >> 4;
        const int stride = 2 * NWARP;
        const __half2 h2z = __floats2half2_rn(0.f, 0.f);
        int w = gw * 2;
        int dgC, stC, dgN = 0, stN = 0;
        int s0C = 0, s1C = 0, s2C = 0, s3C = 0;
        {
            int myn = w + nsel;
            dgC = g_deg[myn]; stC = g_woff[myn];
            if (grp      < dgC) s0C = g_csrc[stC + grp];
            if (grp + 4  < dgC) s1C = g_csrc[stC + grp + 4];
            if (grp + 8  < dgC) s2C = g_csrc[stC + grp + 8];
            if (grp + 12 < dgC) s3C = g_csrc[stC + grp + 12];
            int wn = myn + stride;
            if (wn < NUM_N) { dgN = g_deg[wn]; stN = g_woff[wn]; }
        }
        for (; w < NUM_N; w += stride) {
            int curn = w + nsel;
            int wn2 = curn + 2 * stride;
            int dgN2 = 0, stN2 = 0;
            if (wn2 < NUM_N) { dgN2 = g_deg[wn2]; stN2 = g_woff[wn2]; }
            int s0N = 0, s1N = 0, s2N = 0, s3N = 0;
            if (grp      < dgN) s0N = g_csrc[stN + grp];
            if (grp + 4  < dgN) s1N = g_csrc[stN + grp + 4];
            if (grp + 8  < dgN) s2N = g_csrc[stN + grp + 8];
            if (grp + 12 < dgN) s3N = g_csrc[stN + grp + 12];
            __half2 m0 = h2z, m1 = h2z, n0 = h2z, n1 = h2z;
            __half2 o0 = h2z, o1 = h2z, p0 = h2z, p1 = h2z;
            if (grp      < dgC) gatherh2(g_qh, s0C, sub, m0, m1);
            if (grp + 4  < dgC) gatherh2(g_qh, s1C, sub, n0, n1);
            if (grp + 8  < dgC) gatherh2(g_qh, s2C, sub, o0, o1);
            if (grp + 12 < dgC) gatherh2(g_qh, s3C, sub, p0, p1);
            for (int e = grp + 16; e < dgC; e += 16) {
                int t0 = g_csrc[stC + e];
                int t1 = (e + 4  < dgC) ? g_csrc[stC + e + 4]  : 0;
                int t2 = (e + 8  < dgC) ? g_csrc[stC + e + 8]  : 0;
                int t3 = (e + 12 < dgC) ? g_csrc[stC + e + 12] : 0;
                gatherh2(g_qh, t0, sub, m0, m1);
                if (e + 4  < dgC) gatherh2(g_qh, t1, sub, n0, n1);
                if (e + 8  < dgC) gatherh2(g_qh, t2, sub, o0, o1);
                if (e + 12 < dgC) gatherh2(g_qh, t3, sub, p0, p1);
            }
            float2 fm0 = __half22float2(m0), fm1 = __half22float2(m1);
            float2 fn0 = __half22float2(n0), fn1 = __half22float2(n1);
            float2 fo0 = __half22float2(o0), fo1 = __half22float2(o1);
            float2 fp0 = __half22float2(p0), fp1 = __half22float2(p1);
            float ax = (fm0.x + fn0.x) + (fo0.x + fp0.x);
            float ay = (fm0.y + fn0.y) + (fo0.y + fp0.y);
            float az = (fm1.x + fn1.x) + (fo1.x + fp1.x);
            float aw = (fm1.y + fn1.y) + (fo1.y + fp1.y);
            #pragma unroll
            for (int o = 4; o < 16; o <<= 1) {
                ax += __shfl_xor_sync(~0u, ax, o);
                ay += __shfl_xor_sync(~0u, ay, o);
                az += __shfl_xor_sync(~0u, az, o);
                aw += __shfl_xor_sync(~0u, aw, o);
            }
            if ((lane & 12) == 0) {
                float dvd = g_dinv[curn];
                float qx, qy, qz, qw;
                read16h(g_qh, curn, sub, qx, qy, qz, qw);
                float4 o;
                o.x = dvd * (ax + qx); o.y = dvd * (ay + qy);
                o.z = dvd * (az + qz); o.w = dvd * (aw + qw);
                ((float4*)g_r)[(size_t)curn * 4 + sub] = o;
            }
            dgC = dgN; stC = stN; dgN = dgN2; stN = stN2;
            s0C = s0N; s1C = s1N; s2C = s2N; s3C = s3N;
        }
    }
    grid_sync(5);

    // ================= P6: pool + gemm2 + mlp (blocks 0..127) ==============
    if (bid < NUM_G) {
        for (int i = tid; i < 512; i += TPB) w2s[i] = ((const float4*)W2)[i];
        __syncthreads();
        const int g = bid;
        const int cnt = g_pcnt2[g];
        const int start = g_boff[g];
        float4 bv = ((const float4*)b2)[lane];
        float4 sum = make_float4(0.f, 0.f, 0.f, 0.f);
        int i = wid;
        float rvN = 0.f;
        if (i < cnt) {
            int n = g_bnode[start + i];
            rvN = (lane < 16) ? g_r[n * 16 + lane] : 0.f;
        }
        for (; i < cnt; i += 32) {
            float rv = rvN;
            int in2 = i + 32;
            if (in2 < cnt) {
                int n2 = g_bnode[start + in2];
                rvN = (lane < 16) ? g_r[n2 * 16 + lane] : 0.f;
            }
            float4 acc = bv;
            #pragma unroll
            for (int k = 0; k < 16; k++) {
                float s = __shfl_sync(~0u, rv, k);
                float4 wv = w2s[k * 32 + lane];
                acc.x = fmaf(s, wv.x, acc.x); acc.y = fmaf(s, wv.y, acc.y);
                acc.z = fmaf(s, wv.z, acc.z); acc.w = fmaf(s, wv.w, acc.w);
            }
            sum.x += fmaxf(acc.x, 0.f); sum.y += fmaxf(acc.y, 0.f);
            sum.z += fmaxf(acc.z, 0.f); sum.w += fmaxf(acc.w, 0.f);
        }
        red[wid * 32 + lane] = sum;
        __syncthreads();
        if (tid < 32) {
            float4 tot = red[tid];
            #pragma unroll
            for (int w2 = 1; w2 < 32; w2++) {
                float4 vv = red[w2 * 32 + tid];
                tot.x += vv.x; tot.y += vv.y; tot.z += vv.z; tot.w += vv.w;
            }
            float inv = 1.f / fmaxf((float)cnt, 1.f);
            ps[tid * 4 + 0] = tot.x * inv; ps[tid * 4 + 1] = tot.y * inv;
            ps[tid * 4 + 2] = tot.z * inv; ps[tid * 4 + 3] = tot.w * inv;
        }
        __syncthreads();
        if (tid < 128) {
            float acc = Lb1[tid];
            #pragma unroll 8
            for (int k = 0; k < 128; k++) acc = fmaf(ps[k], LW1[k * 128 + tid], acc);
            z1[tid] = fmaxf(acc, 0.f);
        }
        __syncthreads();
        if (tid < 2) {
            float a = Lb2[tid];
            for (int k = 0; k < 128; k++) a = fmaf(z1[k], LW2[k * 2 + tid], a);
            z2[tid] = a;
        }
        __syncthreads();
        if (tid == 0) {
            float m = fmaxf(z2[0], z2[1]);
            float lse = m + logf(expf(z2[0] - m) + expf(z2[1] - m));
            out[g * 2 + 0] = z2[0] - lse;
            out[g * 2 + 1] = z2[1] - lse;
        }
    } else {
        for (int i = (bid - NUM_G) * TPB + tid; i < NUM_N; i += (GRID - NUM_G) * TPB)
            g_deg[i] = 0;
    }
}

// -------- launch --------
extern "C" void kernel_launch(void* const* d_in, const int* in_sizes, int n_in,
                              void* d_out, int out_size) {
    const float* x   = (const float*)d_in[0];
    const void*  ei  = d_in[1];
    const void*  bat = d_in[2];
    const float* W1  = (const float*)d_in[3];
    const float* b1  = (const float*)d_in[4];
    const float* W2  = (const float*)d_in[5];
    const float* b2  = (const float*)d_in[6];
    const float* LW1 = (const float*)d_in[7];
    const float* Lb1 = (const float*)d_in[8];
    const float* LW2 = (const float*)d_in[9];
    const float* Lb2 = (const float*)d_in[10];
    float* out = (float*)d_out;

    mega_kernel<<<GRID, TPB>>>(x, ei, bat, W1, b1, W2, b2,
                               LW1, Lb1, LW2, Lb2, out);
}